// round 1
// baseline (speedup 1.0000x reference)
#include <cuda_runtime.h>

#define NMAX 50048
#define EMAX 1600000

// ---------------- scratch (static device globals; no allocation) ----------------
__device__ float g_bufA[(size_t)NMAX * 256];
__device__ float g_bufB[(size_t)NMAX * 256];
__device__ int   g_csr_src[EMAX];
__device__ float g_csr_w[EMAX];
__device__ int   g_cnt[NMAX];        // histogram counts, then scatter cursor
__device__ int   g_row_ptr[NMAX + 1];
__device__ int   g_perm[NMAX];       // nodes grouped by label
__device__ int   g_lab_cnt[4];
__device__ int   g_lab_off[5];
__device__ int   g_lab_cur[4];

// ---------------- CSR / grouping build ----------------
__global__ void k_hist_edges(const int* __restrict__ dst, int E) {
    int i = blockIdx.x * blockDim.x + threadIdx.x;
    int stride = gridDim.x * blockDim.x;
    for (; i < E; i += stride) atomicAdd(&g_cnt[dst[i]], 1);
}

__global__ void k_hist_labels(const int* __restrict__ lab, int N) {
    int i = blockIdx.x * blockDim.x + threadIdx.x;
    int stride = gridDim.x * blockDim.x;
    for (; i < N; i += stride) atomicAdd(&g_lab_cnt[lab[i]], 1);
}

// single block, 256 threads: exclusive scan of g_cnt -> g_row_ptr, reset cursor,
// plus tiny label-offset scan
__global__ void k_scan(int N) {
    int tid = threadIdx.x;
    int chunk = (N + 255) / 256;
    int b = tid * chunk;
    int e = b + chunk; if (e > N) e = N;
    int s = 0;
    for (int i = b; i < e && i < N; i++) s += g_cnt[i];

    __shared__ int sm[256];
    sm[tid] = s;
    __syncthreads();
    // Hillis-Steele inclusive scan
    for (int d = 1; d < 256; d <<= 1) {
        int v = (tid >= d) ? sm[tid - d] : 0;
        __syncthreads();
        sm[tid] += v;
        __syncthreads();
    }
    int run = sm[tid] - s;   // exclusive prefix of this chunk
    for (int i = b; i < e && i < N; i++) {
        int c = g_cnt[i];
        g_row_ptr[i] = run;
        g_cnt[i] = run;      // cursor for edge scatter
        run += c;
    }
    if (e == N && b <= N) g_row_ptr[N] = run;  // total (all such threads write same value)

    if (tid == 0) {
        int o = 0;
        for (int i = 0; i < 4; i++) { g_lab_off[i] = o; g_lab_cur[i] = o; o += g_lab_cnt[i]; }
        g_lab_off[4] = o;
    }
}

__global__ void k_scatter_perm(const int* __restrict__ lab, int N) {
    int i = blockIdx.x * blockDim.x + threadIdx.x;
    int stride = gridDim.x * blockDim.x;
    for (; i < N; i += stride) {
        int p = atomicAdd(&g_lab_cur[lab[i]], 1);
        g_perm[p] = i;
    }
}

__global__ void k_scatter_edges(const int* __restrict__ src, const int* __restrict__ dst,
                                const float* __restrict__ w, int E) {
    int i = blockIdx.x * blockDim.x + threadIdx.x;
    int stride = gridDim.x * blockDim.x;
    for (; i < E; i += stride) {
        int p = atomicAdd(&g_cnt[dst[i]], 1);
        g_csr_src[p] = src[i];
        g_csr_w[p] = w[i];
    }
}

// ---------------- grouped dense: S[n,:] = X[n,:] @ W[label(n)] ----------------
// BM=128, BK=16, 256 threads, 8 x TN per-thread tile.
template <int BN, int TN>
__global__ void __launch_bounds__(256, 2)
k_gemm(const float* __restrict__ X, const float* __restrict__ Wt,
       float* __restrict__ S, int K, int NOUT) {
    const int BM = 128, BK = 16;
    __shared__ float As[BK * BM];
    __shared__ float Bs[BK * BN];
    __shared__ int snode[BM];

    int tid = threadIdx.x;
    int bx = blockIdx.x;

    int c0 = g_lab_cnt[0], c1 = g_lab_cnt[1], c2 = g_lab_cnt[2], c3 = g_lab_cnt[3];
    int t0 = (c0 + BM - 1) / BM, t1 = (c1 + BM - 1) / BM,
        t2 = (c2 + BM - 1) / BM, t3 = (c3 + BM - 1) / BM;
    int g, tile;
    if      (bx < t0)                { g = 0; tile = bx; }
    else if (bx < t0 + t1)           { g = 1; tile = bx - t0; }
    else if (bx < t0 + t1 + t2)      { g = 2; tile = bx - t0 - t1; }
    else if (bx < t0 + t1 + t2 + t3) { g = 3; tile = bx - t0 - t1 - t2; }
    else return;
    int cnt = g_lab_cnt[g];
    int off = g_lab_off[g];

    if (tid < BM) {
        int idx = tile * BM + tid;
        snode[tid] = (idx < cnt) ? g_perm[off + idx] : -1;
    }
    __syncthreads();

    const float* Wg = Wt + (size_t)g * K * NOUT + (size_t)blockIdx.y * BN;

    // A loader mapping: each thread owns one row-half (8 consecutive k)
    int am = tid & 127;
    int ak = (tid >> 7) * 8;  // 0 or 8
    int anode = snode[am];
    const float* aptr = X + (size_t)(anode < 0 ? 0 : anode) * K + ak;

    int tx = tid & 15, ty = tid >> 4;
    int ty8 = ty * 8;
    int txT = tx * TN;

    float acc[8][TN];
#pragma unroll
    for (int i = 0; i < 8; i++)
#pragma unroll
        for (int j = 0; j < TN; j++) acc[i][j] = 0.0f;

    for (int k0 = 0; k0 < K; k0 += BK) {
        // global prefetch
        float4 a0 = *(const float4*)(aptr + k0);
        float4 a1 = *(const float4*)(aptr + k0 + 4);
        float4 b0, b1;
        int bn, bk;
        if (BN == 128) {
            bn = (tid & 31) * 4;
            bk = tid >> 5;  // 0..7 (and bk+8)
            b0 = *(const float4*)(Wg + (size_t)(k0 + bk) * NOUT + bn);
            b1 = *(const float4*)(Wg + (size_t)(k0 + bk + 8) * NOUT + bn);
        } else {  // BN == 64
            bn = (tid & 15) * 4;
            bk = tid >> 4;  // 0..15
            b0 = *(const float4*)(Wg + (size_t)(k0 + bk) * NOUT + bn);
        }

        __syncthreads();  // previous tile consumed
        As[(ak + 0) * BM + am] = a0.x;
        As[(ak + 1) * BM + am] = a0.y;
        As[(ak + 2) * BM + am] = a0.z;
        As[(ak + 3) * BM + am] = a0.w;
        As[(ak + 4) * BM + am] = a1.x;
        As[(ak + 5) * BM + am] = a1.y;
        As[(ak + 6) * BM + am] = a1.z;
        As[(ak + 7) * BM + am] = a1.w;
        if (BN == 128) {
            *(float4*)&Bs[bk * BN + bn] = b0;
            *(float4*)&Bs[(bk + 8) * BN + bn] = b1;
        } else {
            *(float4*)&Bs[bk * BN + bn] = b0;
        }
        __syncthreads();

#pragma unroll
        for (int kk = 0; kk < BK; kk++) {
            float4 ar0 = *(const float4*)&As[kk * BM + ty8];
            float4 ar1 = *(const float4*)&As[kk * BM + ty8 + 4];
            float a[8] = {ar0.x, ar0.y, ar0.z, ar0.w, ar1.x, ar1.y, ar1.z, ar1.w};
            float bvals[TN];
            if (TN == 8) {
                float4 br0 = *(const float4*)&Bs[kk * BN + txT];
                float4 br1 = *(const float4*)&Bs[kk * BN + txT + 4];
                bvals[0] = br0.x; bvals[1] = br0.y; bvals[2] = br0.z; bvals[3] = br0.w;
                bvals[4] = br1.x; bvals[5] = br1.y; bvals[6] = br1.z; bvals[7] = br1.w;
            } else {
                float4 br0 = *(const float4*)&Bs[kk * BN + txT];
                bvals[0] = br0.x; bvals[1] = br0.y; bvals[2] = br0.z; bvals[3] = br0.w;
            }
#pragma unroll
            for (int i = 0; i < 8; i++)
#pragma unroll
                for (int j = 0; j < TN; j++) acc[i][j] = fmaf(a[i], bvals[j], acc[i][j]);
        }
    }

    int ncol0 = blockIdx.y * BN + txT;
#pragma unroll
    for (int i = 0; i < 8; i++) {
        int node = snode[ty8 + i];
        if (node >= 0) {
            float* o = S + (size_t)node * NOUT + ncol0;
            if (TN == 8) {
                float4 v0 = {acc[i][0], acc[i][1], acc[i][2], acc[i][3]};
                float4 v1 = {acc[i][4], acc[i][5], acc[i][6], acc[i][7]};
                *(float4*)o = v0;
                *(float4*)(o + 4) = v1;
            } else {
                float4 v0 = {acc[i][0], acc[i][1], acc[i][2], acc[i][3]};
                *(float4*)o = v0;
            }
        }
    }
}

// ---------------- sparse aggregation (gather by dst, CSR) ----------------
__device__ __forceinline__ void fma4(float4& a, float w, const float4& v) {
    a.x = fmaf(w, v.x, a.x);
    a.y = fmaf(w, v.y, a.y);
    a.z = fmaf(w, v.z, a.z);
    a.w = fmaf(w, v.w, a.w);
}

template <int WID>
__global__ void __launch_bounds__(256)
k_spmm(const float* __restrict__ S, float* __restrict__ O,
       const float* __restrict__ bias, int N, int relu) {
    int wid = (blockIdx.x * blockDim.x + threadIdx.x) >> 5;
    int lane = threadIdx.x & 31;
    if (wid >= N) return;
    int s = g_row_ptr[wid], e = g_row_ptr[wid + 1];

    if (WID == 256) {
        float4 acc0 = {0, 0, 0, 0}, acc1 = {0, 0, 0, 0};
        int i = s;
        for (; i + 4 <= e; i += 4) {
            int s0 = g_csr_src[i], s1 = g_csr_src[i + 1];
            int s2 = g_csr_src[i + 2], s3 = g_csr_src[i + 3];
            float w0 = g_csr_w[i], w1 = g_csr_w[i + 1];
            float w2 = g_csr_w[i + 2], w3 = g_csr_w[i + 3];
            const float4* p0 = (const float4*)(S + (size_t)s0 * 256);
            const float4* p1 = (const float4*)(S + (size_t)s1 * 256);
            const float4* p2 = (const float4*)(S + (size_t)s2 * 256);
            const float4* p3 = (const float4*)(S + (size_t)s3 * 256);
            float4 v00 = p0[lane], v01 = p0[32 + lane];
            float4 v10 = p1[lane], v11 = p1[32 + lane];
            float4 v20 = p2[lane], v21 = p2[32 + lane];
            float4 v30 = p3[lane], v31 = p3[32 + lane];
            fma4(acc0, w0, v00); fma4(acc1, w0, v01);
            fma4(acc0, w1, v10); fma4(acc1, w1, v11);
            fma4(acc0, w2, v20); fma4(acc1, w2, v21);
            fma4(acc0, w3, v30); fma4(acc1, w3, v31);
        }
        for (; i < e; i++) {
            int s0 = g_csr_src[i];
            float w0 = g_csr_w[i];
            const float4* p0 = (const float4*)(S + (size_t)s0 * 256);
            float4 v00 = p0[lane], v01 = p0[32 + lane];
            fma4(acc0, w0, v00); fma4(acc1, w0, v01);
        }
        float4 b0 = ((const float4*)bias)[lane];
        float4 b1 = ((const float4*)bias)[32 + lane];
        acc0.x += b0.x; acc0.y += b0.y; acc0.z += b0.z; acc0.w += b0.w;
        acc1.x += b1.x; acc1.y += b1.y; acc1.z += b1.z; acc1.w += b1.w;
        if (relu) {
            acc0.x = fmaxf(acc0.x, 0.f); acc0.y = fmaxf(acc0.y, 0.f);
            acc0.z = fmaxf(acc0.z, 0.f); acc0.w = fmaxf(acc0.w, 0.f);
            acc1.x = fmaxf(acc1.x, 0.f); acc1.y = fmaxf(acc1.y, 0.f);
            acc1.z = fmaxf(acc1.z, 0.f); acc1.w = fmaxf(acc1.w, 0.f);
        }
        float4* o = (float4*)(O + (size_t)wid * 256);
        o[lane] = acc0;
        o[32 + lane] = acc1;
    } else {  // WID == 64
        float2 acc = {0, 0};
        int i = s;
        for (; i + 4 <= e; i += 4) {
            int s0 = g_csr_src[i], s1 = g_csr_src[i + 1];
            int s2 = g_csr_src[i + 2], s3 = g_csr_src[i + 3];
            float w0 = g_csr_w[i], w1 = g_csr_w[i + 1];
            float w2 = g_csr_w[i + 2], w3 = g_csr_w[i + 3];
            float2 v0 = ((const float2*)(S + (size_t)s0 * 64))[lane];
            float2 v1 = ((const float2*)(S + (size_t)s1 * 64))[lane];
            float2 v2 = ((const float2*)(S + (size_t)s2 * 64))[lane];
            float2 v3 = ((const float2*)(S + (size_t)s3 * 64))[lane];
            acc.x = fmaf(w0, v0.x, acc.x); acc.y = fmaf(w0, v0.y, acc.y);
            acc.x = fmaf(w1, v1.x, acc.x); acc.y = fmaf(w1, v1.y, acc.y);
            acc.x = fmaf(w2, v2.x, acc.x); acc.y = fmaf(w2, v2.y, acc.y);
            acc.x = fmaf(w3, v3.x, acc.x); acc.y = fmaf(w3, v3.y, acc.y);
        }
        for (; i < e; i++) {
            int s0 = g_csr_src[i];
            float w0 = g_csr_w[i];
            float2 v0 = ((const float2*)(S + (size_t)s0 * 64))[lane];
            acc.x = fmaf(w0, v0.x, acc.x); acc.y = fmaf(w0, v0.y, acc.y);
        }
        float2 b = ((const float2*)bias)[lane];
        acc.x += b.x; acc.y += b.y;
        if (relu) { acc.x = fmaxf(acc.x, 0.f); acc.y = fmaxf(acc.y, 0.f); }
        ((float2*)(O + (size_t)wid * 64))[lane] = acc;
    }
}

// ---------------- launch ----------------
extern "C" void kernel_launch(void* const* d_in, const int* in_sizes, int n_in,
                              void* d_out, int out_size) {
    const float* x    = (const float*)d_in[0];
    const int*   esrc = (const int*)d_in[1];
    const int*   edst = (const int*)d_in[2];
    const float* ew   = (const float*)d_in[3];
    const int*   lab  = (const int*)d_in[4];
    const float* W1   = (const float*)d_in[5];
    const float* b1   = (const float*)d_in[6];
    const float* W2   = (const float*)d_in[7];
    const float* b2   = (const float*)d_in[8];
    const float* W3   = (const float*)d_in[9];
    const float* b3   = (const float*)d_in[10];
    float* out = (float*)d_out;

    int N = in_sizes[4];
    int E = in_sizes[1];

    void *p_cnt = nullptr, *p_labcnt = nullptr, *p_bufA = nullptr, *p_bufB = nullptr;
    cudaGetSymbolAddress(&p_cnt, g_cnt);
    cudaGetSymbolAddress(&p_labcnt, g_lab_cnt);
    cudaGetSymbolAddress(&p_bufA, g_bufA);
    cudaGetSymbolAddress(&p_bufB, g_bufB);
    float* bufA = (float*)p_bufA;
    float* bufB = (float*)p_bufB;

    cudaMemsetAsync(p_cnt, 0, (size_t)N * sizeof(int), 0);
    cudaMemsetAsync(p_labcnt, 0, 4 * sizeof(int), 0);

    const int tpb = 256;
    k_hist_edges<<<1024, tpb>>>(edst, E);
    k_hist_labels<<<128, tpb>>>(lab, N);
    k_scan<<<1, 256>>>(N);
    k_scatter_perm<<<128, tpb>>>(lab, N);
    k_scatter_edges<<<1024, tpb>>>(esrc, edst, ew, E);

    int rt = (N + 127) / 128 + 4;        // row tiles incl. per-group padding
    int spmm_blocks = (N * 32 + tpb - 1) / tpb;

    // layer 1
    k_gemm<128, 8><<<dim3(rt, 2), 256>>>(x, W1, bufA, 256, 256);
    k_spmm<256><<<spmm_blocks, tpb>>>(bufA, bufB, b1, N, 1);
    // layer 2
    k_gemm<128, 8><<<dim3(rt, 2), 256>>>(bufB, W2, bufA, 256, 256);
    k_spmm<256><<<spmm_blocks, tpb>>>(bufA, bufB, b2, N, 1);
    // layer 3
    k_gemm<64, 4><<<dim3(rt, 1), 256>>>(bufB, W3, bufA, 256, 64);
    k_spmm<64><<<spmm_blocks, tpb>>>(bufA, out, b3, N, 0);
}

// round 2
// speedup vs baseline: 1.2737x; 1.2737x over previous
#include <cuda_runtime.h>
#include <cstdint>

#define NMAX 50048
#define EMAX 1600000

// ---------------- scratch (static device globals; no allocation) ----------------
__device__ float g_bufA[(size_t)NMAX * 256];
__device__ float g_bufB[(size_t)NMAX * 256];
__device__ int   g_csr_src[EMAX];
__device__ float g_csr_w[EMAX];
__device__ int   g_cnt[NMAX];        // histogram counts, then scatter cursor
__device__ int   g_row_ptr[NMAX + 1];
__device__ int   g_perm[NMAX];       // nodes grouped by label
__device__ int   g_lab_cnt[4];
__device__ int   g_lab_off[5];
__device__ int   g_lab_cur[4];

// ---------------- packed f32x2 helpers (sm_103a) ----------------
__device__ __forceinline__ uint64_t dup2(float a) {
    uint64_t r;
    unsigned u = __float_as_uint(a);
    asm("mov.b64 %0, {%1, %1};" : "=l"(r) : "r"(u));
    return r;
}
__device__ __forceinline__ void fma2(uint64_t& c, uint64_t a, uint64_t b) {
    asm("fma.rn.f32x2 %0, %1, %2, %3;" : "=l"(c) : "l"(a), "l"(b), "l"(c));
}
__device__ __forceinline__ float2 unpk(uint64_t v) {
    float2 f;
    asm("mov.b64 {%0, %1}, %2;" : "=f"(f.x), "=f"(f.y) : "l"(v));
    return f;
}

// ---------------- CSR / grouping build ----------------
__global__ void k_hist_edges(const int* __restrict__ dst, int E) {
    int i = blockIdx.x * blockDim.x + threadIdx.x;
    int stride = gridDim.x * blockDim.x;
    for (; i < E; i += stride) atomicAdd(&g_cnt[dst[i]], 1);
}

__global__ void k_hist_labels(const int* __restrict__ lab, int N) {
    __shared__ int c[4];
    if (threadIdx.x < 4) c[threadIdx.x] = 0;
    __syncthreads();
    int i = blockIdx.x * blockDim.x + threadIdx.x;
    int stride = gridDim.x * blockDim.x;
    for (; i < N; i += stride) atomicAdd(&c[lab[i]], 1);
    __syncthreads();
    if (threadIdx.x < 4 && c[threadIdx.x]) atomicAdd(&g_lab_cnt[threadIdx.x], c[threadIdx.x]);
}

// 1024 threads, single block: exclusive scan of g_cnt -> g_row_ptr, reset cursor
__global__ void k_scan_rows(int N) {
    int tid = threadIdx.x;
    int chunk = (N + 1023) / 1024;
    int b = tid * chunk;
    int e = b + chunk; if (e > N) e = N;
    int s = 0;
    for (int i = b; i < e; i++) s += g_cnt[i];

    __shared__ int sm[1024];
    sm[tid] = s;
    __syncthreads();
    for (int d = 1; d < 1024; d <<= 1) {
        int v = (tid >= d) ? sm[tid - d] : 0;
        __syncthreads();
        sm[tid] += v;
        __syncthreads();
    }
    int run = sm[tid] - s;
    for (int i = b; i < e; i++) {
        int c = g_cnt[i];
        g_row_ptr[i] = run;
        g_cnt[i] = run;      // cursor for edge scatter
        run += c;
    }
    if (tid == 1023) g_row_ptr[N] = sm[1023];
}

__global__ void k_scan_labels() {
    if (threadIdx.x == 0) {
        int o = 0;
        for (int i = 0; i < 4; i++) { g_lab_off[i] = o; g_lab_cur[i] = o; o += g_lab_cnt[i]; }
        g_lab_off[4] = o;
    }
}

// block-aggregated scatter: one global atomic per label per block
__global__ void k_scatter_perm(const int* __restrict__ lab, int N) {
    __shared__ int c[4], base[4];
    if (threadIdx.x < 4) c[threadIdx.x] = 0;
    __syncthreads();
    int i = blockIdx.x * blockDim.x + threadIdx.x;
    int l = 0, local = 0;
    bool valid = (i < N);
    if (valid) {
        l = lab[i];
        local = atomicAdd(&c[l], 1);
    }
    __syncthreads();
    if (threadIdx.x < 4)
        base[threadIdx.x] = c[threadIdx.x] ? atomicAdd(&g_lab_cur[threadIdx.x], c[threadIdx.x]) : 0;
    __syncthreads();
    if (valid) g_perm[base[l] + local] = i;
}

__global__ void k_scatter_edges(const int* __restrict__ src, const int* __restrict__ dst,
                                const float* __restrict__ w, int E) {
    int i = blockIdx.x * blockDim.x + threadIdx.x;
    int stride = gridDim.x * blockDim.x;
    for (; i < E; i += stride) {
        int p = atomicAdd(&g_cnt[dst[i]], 1);
        g_csr_src[p] = src[i];
        g_csr_w[p] = w[i];
    }
}

// ---------------- grouped dense: S[n,:] = X[n,:] @ W[label(n)] ----------------
// BM=128, BK=16, 256 threads, 8 x TN per-thread tile, packed f32x2 math.
template <int BN, int TN>
__global__ void __launch_bounds__(256, 2)
k_gemm(const float* __restrict__ X, const float* __restrict__ Wt,
       float* __restrict__ S, int K, int NOUT) {
    const int BM = 128, BK = 16;
    const int NP = TN / 2;
    __shared__ float As[BK * BM];
    __shared__ float Bs[BK * BN];
    __shared__ int snode[BM];

    int tid = threadIdx.x;
    int bx = blockIdx.x;

    int c0 = g_lab_cnt[0], c1 = g_lab_cnt[1], c2 = g_lab_cnt[2], c3 = g_lab_cnt[3];
    int t0 = (c0 + BM - 1) / BM, t1 = (c1 + BM - 1) / BM,
        t2 = (c2 + BM - 1) / BM, t3 = (c3 + BM - 1) / BM;
    int g, tile;
    if      (bx < t0)                { g = 0; tile = bx; }
    else if (bx < t0 + t1)           { g = 1; tile = bx - t0; }
    else if (bx < t0 + t1 + t2)      { g = 2; tile = bx - t0 - t1; }
    else if (bx < t0 + t1 + t2 + t3) { g = 3; tile = bx - t0 - t1 - t2; }
    else return;
    int cnt = g_lab_cnt[g];
    int off = g_lab_off[g];

    if (tid < BM) {
        int idx = tile * BM + tid;
        snode[tid] = (idx < cnt) ? g_perm[off + idx] : -1;
    }
    __syncthreads();

    const float* Wg = Wt + (size_t)g * K * NOUT + (size_t)blockIdx.y * BN;

    // A loader mapping: each thread owns one row-half (8 consecutive k)
    int am = tid & 127;
    int ak = (tid >> 7) * 8;  // 0 or 8
    int anode = snode[am];
    const float* aptr = X + (size_t)(anode < 0 ? 0 : anode) * K + ak;

    int tx = tid & 15, ty = tid >> 4;
    int ty8 = ty * 8;
    int txT = tx * TN;

    uint64_t acc[8][NP];
#pragma unroll
    for (int i = 0; i < 8; i++)
#pragma unroll
        for (int j = 0; j < NP; j++) acc[i][j] = 0ull;

    for (int k0 = 0; k0 < K; k0 += BK) {
        // global prefetch
        float4 a0 = *(const float4*)(aptr + k0);
        float4 a1 = *(const float4*)(aptr + k0 + 4);
        float4 b0, b1;
        int bn, bk;
        if (BN == 128) {
            bn = (tid & 31) * 4;
            bk = tid >> 5;  // 0..7 (and bk+8)
            b0 = *(const float4*)(Wg + (size_t)(k0 + bk) * NOUT + bn);
            b1 = *(const float4*)(Wg + (size_t)(k0 + bk + 8) * NOUT + bn);
        } else {  // BN == 64
            bn = (tid & 15) * 4;
            bk = tid >> 4;  // 0..15
            b0 = *(const float4*)(Wg + (size_t)(k0 + bk) * NOUT + bn);
        }

        __syncthreads();  // previous tile consumed
        As[(ak + 0) * BM + am] = a0.x;
        As[(ak + 1) * BM + am] = a0.y;
        As[(ak + 2) * BM + am] = a0.z;
        As[(ak + 3) * BM + am] = a0.w;
        As[(ak + 4) * BM + am] = a1.x;
        As[(ak + 5) * BM + am] = a1.y;
        As[(ak + 6) * BM + am] = a1.z;
        As[(ak + 7) * BM + am] = a1.w;
        if (BN == 128) {
            *(float4*)&Bs[bk * BN + bn] = b0;
            *(float4*)&Bs[(bk + 8) * BN + bn] = b1;
        } else {
            *(float4*)&Bs[bk * BN + bn] = b0;
        }
        __syncthreads();

#pragma unroll
        for (int kk = 0; kk < BK; kk++) {
            float4 ar0 = *(const float4*)&As[kk * BM + ty8];
            float4 ar1 = *(const float4*)&As[kk * BM + ty8 + 4];
            float a[8] = {ar0.x, ar0.y, ar0.z, ar0.w, ar1.x, ar1.y, ar1.z, ar1.w};
            uint64_t bp[NP];
            {
                ulonglong2 q0 = *(const ulonglong2*)&Bs[kk * BN + txT];
                bp[0] = q0.x; bp[1] = q0.y;
                if (NP == 4) {
                    ulonglong2 q1 = *(const ulonglong2*)&Bs[kk * BN + txT + 4];
                    bp[2] = q1.x; bp[3] = q1.y;
                }
            }
#pragma unroll
            for (int i = 0; i < 8; i++) {
                uint64_t ad = dup2(a[i]);
#pragma unroll
                for (int j = 0; j < NP; j++) fma2(acc[i][j], ad, bp[j]);
            }
        }
    }

    int ncol0 = blockIdx.y * BN + txT;
#pragma unroll
    for (int i = 0; i < 8; i++) {
        int node = snode[ty8 + i];
        if (node >= 0) {
            float* o = S + (size_t)node * NOUT + ncol0;
            float2 f0 = unpk(acc[i][0]);
            float2 f1 = unpk(acc[i][1]);
            float4 v0 = {f0.x, f0.y, f1.x, f1.y};
            *(float4*)o = v0;
            if (NP == 4) {
                float2 f2 = unpk(acc[i][2]);
                float2 f3 = unpk(acc[i][3]);
                float4 v1 = {f2.x, f2.y, f3.x, f3.y};
                *(float4*)(o + 4) = v1;
            }
        }
    }
}

// ---------------- sparse aggregation (gather by dst, CSR) ----------------
__device__ __forceinline__ void fma4(float4& a, float w, const float4& v) {
    a.x = fmaf(w, v.x, a.x);
    a.y = fmaf(w, v.y, a.y);
    a.z = fmaf(w, v.z, a.z);
    a.w = fmaf(w, v.w, a.w);
}

template <int WID>
__global__ void __launch_bounds__(256)
k_spmm(const float* __restrict__ S, float* __restrict__ O,
       const float* __restrict__ bias, int N, int relu) {
    int wid = (blockIdx.x * blockDim.x + threadIdx.x) >> 5;
    int lane = threadIdx.x & 31;
    if (wid >= N) return;
    int s = g_row_ptr[wid], e = g_row_ptr[wid + 1];

    if (WID == 256) {
        float4 acc0 = {0, 0, 0, 0}, acc1 = {0, 0, 0, 0};
        int i = s;
        for (; i + 4 <= e; i += 4) {
            int s0 = g_csr_src[i], s1 = g_csr_src[i + 1];
            int s2 = g_csr_src[i + 2], s3 = g_csr_src[i + 3];
            float w0 = g_csr_w[i], w1 = g_csr_w[i + 1];
            float w2 = g_csr_w[i + 2], w3 = g_csr_w[i + 3];
            const float4* p0 = (const float4*)(S + (size_t)s0 * 256);
            const float4* p1 = (const float4*)(S + (size_t)s1 * 256);
            const float4* p2 = (const float4*)(S + (size_t)s2 * 256);
            const float4* p3 = (const float4*)(S + (size_t)s3 * 256);
            float4 v00 = p0[lane], v01 = p0[32 + lane];
            float4 v10 = p1[lane], v11 = p1[32 + lane];
            float4 v20 = p2[lane], v21 = p2[32 + lane];
            float4 v30 = p3[lane], v31 = p3[32 + lane];
            fma4(acc0, w0, v00); fma4(acc1, w0, v01);
            fma4(acc0, w1, v10); fma4(acc1, w1, v11);
            fma4(acc0, w2, v20); fma4(acc1, w2, v21);
            fma4(acc0, w3, v30); fma4(acc1, w3, v31);
        }
        for (; i < e; i++) {
            int s0 = g_csr_src[i];
            float w0 = g_csr_w[i];
            const float4* p0 = (const float4*)(S + (size_t)s0 * 256);
            float4 v00 = p0[lane], v01 = p0[32 + lane];
            fma4(acc0, w0, v00); fma4(acc1, w0, v01);
        }
        float4 b0 = ((const float4*)bias)[lane];
        float4 b1 = ((const float4*)bias)[32 + lane];
        acc0.x += b0.x; acc0.y += b0.y; acc0.z += b0.z; acc0.w += b0.w;
        acc1.x += b1.x; acc1.y += b1.y; acc1.z += b1.z; acc1.w += b1.w;
        if (relu) {
            acc0.x = fmaxf(acc0.x, 0.f); acc0.y = fmaxf(acc0.y, 0.f);
            acc0.z = fmaxf(acc0.z, 0.f); acc0.w = fmaxf(acc0.w, 0.f);
            acc1.x = fmaxf(acc1.x, 0.f); acc1.y = fmaxf(acc1.y, 0.f);
            acc1.z = fmaxf(acc1.z, 0.f); acc1.w = fmaxf(acc1.w, 0.f);
        }
        float4* o = (float4*)(O + (size_t)wid * 256);
        o[lane] = acc0;
        o[32 + lane] = acc1;
    } else {  // WID == 64
        float2 acc = {0, 0};
        int i = s;
        for (; i + 4 <= e; i += 4) {
            int s0 = g_csr_src[i], s1 = g_csr_src[i + 1];
            int s2 = g_csr_src[i + 2], s3 = g_csr_src[i + 3];
            float w0 = g_csr_w[i], w1 = g_csr_w[i + 1];
            float w2 = g_csr_w[i + 2], w3 = g_csr_w[i + 3];
            float2 v0 = ((const float2*)(S + (size_t)s0 * 64))[lane];
            float2 v1 = ((const float2*)(S + (size_t)s1 * 64))[lane];
            float2 v2 = ((const float2*)(S + (size_t)s2 * 64))[lane];
            float2 v3 = ((const float2*)(S + (size_t)s3 * 64))[lane];
            acc.x = fmaf(w0, v0.x, acc.x); acc.y = fmaf(w0, v0.y, acc.y);
            acc.x = fmaf(w1, v1.x, acc.x); acc.y = fmaf(w1, v1.y, acc.y);
            acc.x = fmaf(w2, v2.x, acc.x); acc.y = fmaf(w2, v2.y, acc.y);
            acc.x = fmaf(w3, v3.x, acc.x); acc.y = fmaf(w3, v3.y, acc.y);
        }
        for (; i < e; i++) {
            int s0 = g_csr_src[i];
            float w0 = g_csr_w[i];
            float2 v0 = ((const float2*)(S + (size_t)s0 * 64))[lane];
            acc.x = fmaf(w0, v0.x, acc.x); acc.y = fmaf(w0, v0.y, acc.y);
        }
        float2 b = ((const float2*)bias)[lane];
        acc.x += b.x; acc.y += b.y;
        if (relu) { acc.x = fmaxf(acc.x, 0.f); acc.y = fmaxf(acc.y, 0.f); }
        ((float2*)(O + (size_t)wid * 64))[lane] = acc;
    }
}

// ---------------- launch ----------------
extern "C" void kernel_launch(void* const* d_in, const int* in_sizes, int n_in,
                              void* d_out, int out_size) {
    const float* x    = (const float*)d_in[0];
    const int*   esrc = (const int*)d_in[1];
    const int*   edst = (const int*)d_in[2];
    const float* ew   = (const float*)d_in[3];
    const int*   lab  = (const int*)d_in[4];
    const float* W1   = (const float*)d_in[5];
    const float* b1   = (const float*)d_in[6];
    const float* W2   = (const float*)d_in[7];
    const float* b2   = (const float*)d_in[8];
    const float* W3   = (const float*)d_in[9];
    const float* b3   = (const float*)d_in[10];
    float* out = (float*)d_out;

    int N = in_sizes[4];
    int E = in_sizes[1];

    void *p_cnt = nullptr, *p_labcnt = nullptr, *p_bufA = nullptr, *p_bufB = nullptr;
    cudaGetSymbolAddress(&p_cnt, g_cnt);
    cudaGetSymbolAddress(&p_labcnt, g_lab_cnt);
    cudaGetSymbolAddress(&p_bufA, g_bufA);
    cudaGetSymbolAddress(&p_bufB, g_bufB);
    float* bufA = (float*)p_bufA;
    float* bufB = (float*)p_bufB;

    // side stream + fork/join events (created once; host-side objects only)
    static cudaStream_t s2 = nullptr;
    static cudaEvent_t evFork = nullptr, evJoin = nullptr;
    if (s2 == nullptr) {
        cudaStreamCreateWithFlags(&s2, cudaStreamNonBlocking);
        cudaEventCreateWithFlags(&evFork, cudaEventDisableTiming);
        cudaEventCreateWithFlags(&evJoin, cudaEventDisableTiming);
    }

    const int tpb = 256;

    // ---- fork: edge/CSR build on s2, label grouping + GEMM1 on main ----
    cudaEventRecord(evFork, 0);
    cudaStreamWaitEvent(s2, evFork, 0);

    // s2: CSR by destination
    cudaMemsetAsync(p_cnt, 0, (size_t)N * sizeof(int), s2);
    k_hist_edges<<<1024, tpb, 0, s2>>>(edst, E);
    k_scan_rows<<<1, 1024, 0, s2>>>(N);
    k_scatter_edges<<<1024, tpb, 0, s2>>>(esrc, edst, ew, E);
    cudaEventRecord(evJoin, s2);

    // main: label grouping
    cudaMemsetAsync(p_labcnt, 0, 4 * sizeof(int), 0);
    k_hist_labels<<<128, tpb>>>(lab, N);
    k_scan_labels<<<1, 32>>>();
    k_scatter_perm<<<(N + tpb - 1) / tpb, tpb>>>(lab, N);

    int rt = (N + 127) / 128 + 4;        // row tiles incl. per-group padding
    int spmm_blocks = (N * 32 + tpb - 1) / tpb;

    // layer 1 dense (independent of CSR)
    k_gemm<128, 8><<<dim3(rt, 2), 256>>>(x, W1, bufA, 256, 256);

    // join: CSR must be ready before aggregation
    cudaStreamWaitEvent(0, evJoin, 0);

    k_spmm<256><<<spmm_blocks, tpb>>>(bufA, bufB, b1, N, 1);
    // layer 2
    k_gemm<128, 8><<<dim3(rt, 2), 256>>>(bufB, W2, bufA, 256, 256);
    k_spmm<256><<<spmm_blocks, tpb>>>(bufA, bufB, b2, N, 1);
    // layer 3
    k_gemm<64, 4><<<dim3(rt, 1), 256>>>(bufB, W3, bufA, 256, 64);
    k_spmm<64><<<spmm_blocks, tpb>>>(bufA, out, b3, N, 0);
}

// round 4
// speedup vs baseline: 1.4581x; 1.1448x over previous
#include <cuda_runtime.h>
#include <cuda_fp16.h>
#include <cstdint>

#define NMAX 50048
#define EMAX 1600000

// ---------------- scratch (static device globals; no allocation) ----------------
__device__ float  g_bufA[(size_t)NMAX * 256];   // fp32 node features (ping)
__device__ float  g_bufB[(size_t)NMAX * 256];   // fp32 node features (pong)
__device__ __half g_bufH[(size_t)NMAX * 256];   // fp16 support (GEMM out / SpMM in)
__device__ int    g_csr_src[EMAX];
__device__ float  g_csr_w[EMAX];
__device__ int    g_cnt[NMAX];
__device__ int    g_row_ptr[NMAX + 1];
__device__ int    g_perm[NMAX];
__device__ int    g_lab_cnt[4];
__device__ int    g_lab_off[5];
__device__ int    g_lab_cur[4];

// ---------------- packed f32x2 helpers (sm_103a) ----------------
__device__ __forceinline__ uint64_t dup2(float a) {
    uint64_t r;
    unsigned u = __float_as_uint(a);
    asm("mov.b64 %0, {%1, %1};" : "=l"(r) : "r"(u));
    return r;
}
__device__ __forceinline__ void fma2(uint64_t& c, uint64_t a, uint64_t b) {
    asm("fma.rn.f32x2 %0, %1, %2, %3;" : "=l"(c) : "l"(a), "l"(b), "l"(c));
}
__device__ __forceinline__ float2 unpk(uint64_t v) {
    float2 f;
    asm("mov.b64 {%0, %1}, %2;" : "=f"(f.x), "=f"(f.y) : "l"(v));
    return f;
}

// ---------------- CSR / grouping build ----------------
__global__ void k_hist_edges(const int* __restrict__ dst, int E) {
    int i = blockIdx.x * blockDim.x + threadIdx.x;
    int stride = gridDim.x * blockDim.x;
    for (; i < E; i += stride) atomicAdd(&g_cnt[dst[i]], 1);
}

__global__ void k_hist_labels(const int* __restrict__ lab, int N) {
    __shared__ int c[4];
    if (threadIdx.x < 4) c[threadIdx.x] = 0;
    __syncthreads();
    int i = blockIdx.x * blockDim.x + threadIdx.x;
    int stride = gridDim.x * blockDim.x;
    for (; i < N; i += stride) atomicAdd(&c[lab[i]], 1);
    __syncthreads();
    if (threadIdx.x < 4 && c[threadIdx.x]) atomicAdd(&g_lab_cnt[threadIdx.x], c[threadIdx.x]);
}

__global__ void k_scan_rows(int N) {
    int tid = threadIdx.x;
    int chunk = (N + 1023) / 1024;
    int b = tid * chunk;
    int e = b + chunk; if (e > N) e = N;
    int s = 0;
    for (int i = b; i < e; i++) s += g_cnt[i];

    __shared__ int sm[1024];
    sm[tid] = s;
    __syncthreads();
    for (int d = 1; d < 1024; d <<= 1) {
        int v = (tid >= d) ? sm[tid - d] : 0;
        __syncthreads();
        sm[tid] += v;
        __syncthreads();
    }
    int run = sm[tid] - s;
    for (int i = b; i < e; i++) {
        int c = g_cnt[i];
        g_row_ptr[i] = run;
        g_cnt[i] = run;      // cursor for edge scatter
        run += c;
    }
    if (tid == 1023) g_row_ptr[N] = sm[1023];
}

__global__ void k_scan_labels() {
    if (threadIdx.x == 0) {
        int o = 0;
        for (int i = 0; i < 4; i++) { g_lab_off[i] = o; g_lab_cur[i] = o; o += g_lab_cnt[i]; }
        g_lab_off[4] = o;
    }
}

__global__ void k_scatter_perm(const int* __restrict__ lab, int N) {
    __shared__ int c[4], base[4];
    if (threadIdx.x < 4) c[threadIdx.x] = 0;
    __syncthreads();
    int i = blockIdx.x * blockDim.x + threadIdx.x;
    int l = 0, local = 0;
    bool valid = (i < N);
    if (valid) {
        l = lab[i];
        local = atomicAdd(&c[l], 1);
    }
    __syncthreads();
    if (threadIdx.x < 4)
        base[threadIdx.x] = c[threadIdx.x] ? atomicAdd(&g_lab_cur[threadIdx.x], c[threadIdx.x]) : 0;
    __syncthreads();
    if (valid) g_perm[base[l] + local] = i;
}

__global__ void k_scatter_edges(const int* __restrict__ src, const int* __restrict__ dst,
                                const float* __restrict__ w, int E) {
    int i = blockIdx.x * blockDim.x + threadIdx.x;
    int stride = gridDim.x * blockDim.x;
    for (; i < E; i += stride) {
        int p = atomicAdd(&g_cnt[dst[i]], 1);
        g_csr_src[p] = src[i];
        g_csr_w[p] = w[i];
    }
}

// ---------------- grouped dense: H[n,:] = fp16( X[n,:] @ W[label(n)] ) ----------------
// BM=128, BK=16, 256 threads, 8 x TN per-thread tile, packed f32x2 math.
template <int BN, int TN>
__global__ void __launch_bounds__(256, 2)
k_gemm(const float* __restrict__ X, const float* __restrict__ Wt,
       __half* __restrict__ S, int K, int NOUT) {
    const int BM = 128, BK = 16;
    const int NP = TN / 2;
    __shared__ float As[BK * BM];
    __shared__ float Bs[BK * BN];
    __shared__ int snode[BM];

    int tid = threadIdx.x;
    int bx = blockIdx.x;

    int c0 = g_lab_cnt[0], c1 = g_lab_cnt[1], c2 = g_lab_cnt[2], c3 = g_lab_cnt[3];
    int t0 = (c0 + BM - 1) / BM, t1 = (c1 + BM - 1) / BM,
        t2 = (c2 + BM - 1) / BM, t3 = (c3 + BM - 1) / BM;
    int g, tile;
    if      (bx < t0)                { g = 0; tile = bx; }
    else if (bx < t0 + t1)           { g = 1; tile = bx - t0; }
    else if (bx < t0 + t1 + t2)      { g = 2; tile = bx - t0 - t1; }
    else if (bx < t0 + t1 + t2 + t3) { g = 3; tile = bx - t0 - t1 - t2; }
    else return;
    int cnt = g_lab_cnt[g];
    int off = g_lab_off[g];

    if (tid < BM) {
        int idx = tile * BM + tid;
        snode[tid] = (idx < cnt) ? g_perm[off + idx] : -1;
    }
    __syncthreads();

    const float* Wg = Wt + (size_t)g * K * NOUT + (size_t)blockIdx.y * BN;

    int am = tid & 127;
    int ak = (tid >> 7) * 8;  // 0 or 8
    int anode = snode[am];
    const float* aptr = X + (size_t)(anode < 0 ? 0 : anode) * K + ak;

    int tx = tid & 15, ty = tid >> 4;
    int ty8 = ty * 8;
    int txT = tx * TN;

    uint64_t acc[8][NP];
#pragma unroll
    for (int i = 0; i < 8; i++)
#pragma unroll
        for (int j = 0; j < NP; j++) acc[i][j] = 0ull;

    for (int k0 = 0; k0 < K; k0 += BK) {
        float4 a0 = *(const float4*)(aptr + k0);
        float4 a1 = *(const float4*)(aptr + k0 + 4);
        float4 b0, b1;
        int bn, bk;
        if (BN == 128) {
            bn = (tid & 31) * 4;
            bk = tid >> 5;
            b0 = *(const float4*)(Wg + (size_t)(k0 + bk) * NOUT + bn);
            b1 = *(const float4*)(Wg + (size_t)(k0 + bk + 8) * NOUT + bn);
        } else {  // BN == 64
            bn = (tid & 15) * 4;
            bk = tid >> 4;
            b0 = *(const float4*)(Wg + (size_t)(k0 + bk) * NOUT + bn);
        }

        __syncthreads();
        As[(ak + 0) * BM + am] = a0.x;
        As[(ak + 1) * BM + am] = a0.y;
        As[(ak + 2) * BM + am] = a0.z;
        As[(ak + 3) * BM + am] = a0.w;
        As[(ak + 4) * BM + am] = a1.x;
        As[(ak + 5) * BM + am] = a1.y;
        As[(ak + 6) * BM + am] = a1.z;
        As[(ak + 7) * BM + am] = a1.w;
        if (BN == 128) {
            *(float4*)&Bs[bk * BN + bn] = b0;
            *(float4*)&Bs[(bk + 8) * BN + bn] = b1;
        } else {
            *(float4*)&Bs[bk * BN + bn] = b0;
        }
        __syncthreads();

#pragma unroll
        for (int kk = 0; kk < BK; kk++) {
            float4 ar0 = *(const float4*)&As[kk * BM + ty8];
            float4 ar1 = *(const float4*)&As[kk * BM + ty8 + 4];
            float a[8] = {ar0.x, ar0.y, ar0.z, ar0.w, ar1.x, ar1.y, ar1.z, ar1.w};
            uint64_t bp[NP];
            {
                ulonglong2 q0 = *(const ulonglong2*)&Bs[kk * BN + txT];
                bp[0] = q0.x; bp[1] = q0.y;
                if (NP == 4) {
                    ulonglong2 q1 = *(const ulonglong2*)&Bs[kk * BN + txT + 4];
                    bp[2] = q1.x; bp[3] = q1.y;
                }
            }
#pragma unroll
            for (int i = 0; i < 8; i++) {
                uint64_t ad = dup2(a[i]);
#pragma unroll
                for (int j = 0; j < NP; j++) fma2(acc[i][j], ad, bp[j]);
            }
        }
    }

    int ncol0 = blockIdx.y * BN + txT;
#pragma unroll
    for (int i = 0; i < 8; i++) {
        int node = snode[ty8 + i];
        if (node >= 0) {
            __half* o = S + (size_t)node * NOUT + ncol0;
            float2 f0 = unpk(acc[i][0]);
            float2 f1 = unpk(acc[i][1]);
            __half2 h0 = __float22half2_rn(f0);
            __half2 h1 = __float22half2_rn(f1);
            if (NP == 4) {
                float2 f2 = unpk(acc[i][2]);
                float2 f3 = unpk(acc[i][3]);
                __half2 h2 = __float22half2_rn(f2);
                __half2 h3 = __float22half2_rn(f3);
                uint4 v;
                v.x = *(uint32_t*)&h0; v.y = *(uint32_t*)&h1;
                v.z = *(uint32_t*)&h2; v.w = *(uint32_t*)&h3;
                *(uint4*)o = v;
            } else {
                uint2 v;
                v.x = *(uint32_t*)&h0; v.y = *(uint32_t*)&h1;
                *(uint2*)o = v;
            }
        }
    }
}

// ---------------- sparse aggregation (gather by dst, CSR, fp16 support) ----------------
template <int WID>
__global__ void __launch_bounds__(256)
k_spmm(const __half* __restrict__ S, float* __restrict__ O,
       const float* __restrict__ bias, int N, int relu) {
    int wid = (blockIdx.x * blockDim.x + threadIdx.x) >> 5;
    int lane = threadIdx.x & 31;
    if (wid >= N) return;
    int s = g_row_ptr[wid], e = g_row_ptr[wid + 1];

    if (WID == 256) {
        // each lane owns 8 consecutive columns: lane*8 .. lane*8+7
        float acc[8];
#pragma unroll
        for (int q = 0; q < 8; q++) acc[q] = 0.0f;

        int i = s;
        for (; i + 4 <= e; i += 4) {
            int s0 = g_csr_src[i], s1 = g_csr_src[i + 1];
            int s2 = g_csr_src[i + 2], s3 = g_csr_src[i + 3];
            float w0 = g_csr_w[i], w1 = g_csr_w[i + 1];
            float w2 = g_csr_w[i + 2], w3 = g_csr_w[i + 3];
            uint4 q0 = *(const uint4*)(S + (size_t)s0 * 256 + lane * 8);
            uint4 q1 = *(const uint4*)(S + (size_t)s1 * 256 + lane * 8);
            uint4 q2 = *(const uint4*)(S + (size_t)s2 * 256 + lane * 8);
            uint4 q3 = *(const uint4*)(S + (size_t)s3 * 256 + lane * 8);
#pragma unroll
            for (int h = 0; h < 4; h++) {
                float2 f0 = __half22float2(((const __half2*)&q0)[h]);
                float2 f1 = __half22float2(((const __half2*)&q1)[h]);
                float2 f2 = __half22float2(((const __half2*)&q2)[h]);
                float2 f3 = __half22float2(((const __half2*)&q3)[h]);
                acc[h * 2 + 0] = fmaf(w0, f0.x, acc[h * 2 + 0]);
                acc[h * 2 + 1] = fmaf(w0, f0.y, acc[h * 2 + 1]);
                acc[h * 2 + 0] = fmaf(w1, f1.x, acc[h * 2 + 0]);
                acc[h * 2 + 1] = fmaf(w1, f1.y, acc[h * 2 + 1]);
                acc[h * 2 + 0] = fmaf(w2, f2.x, acc[h * 2 + 0]);
                acc[h * 2 + 1] = fmaf(w2, f2.y, acc[h * 2 + 1]);
                acc[h * 2 + 0] = fmaf(w3, f3.x, acc[h * 2 + 0]);
                acc[h * 2 + 1] = fmaf(w3, f3.y, acc[h * 2 + 1]);
            }
        }
        for (; i < e; i++) {
            int s0 = g_csr_src[i];
            float w0 = g_csr_w[i];
            uint4 q0 = *(const uint4*)(S + (size_t)s0 * 256 + lane * 8);
#pragma unroll
            for (int h = 0; h < 4; h++) {
                float2 f0 = __half22float2(((const __half2*)&q0)[h]);
                acc[h * 2 + 0] = fmaf(w0, f0.x, acc[h * 2 + 0]);
                acc[h * 2 + 1] = fmaf(w0, f0.y, acc[h * 2 + 1]);
            }
        }
        float4 b0 = *(const float4*)(bias + lane * 8);
        float4 b1 = *(const float4*)(bias + lane * 8 + 4);
        acc[0] += b0.x; acc[1] += b0.y; acc[2] += b0.z; acc[3] += b0.w;
        acc[4] += b1.x; acc[5] += b1.y; acc[6] += b1.z; acc[7] += b1.w;
        if (relu) {
#pragma unroll
            for (int q = 0; q < 8; q++) acc[q] = fmaxf(acc[q], 0.0f);
        }
        float4 v0 = {acc[0], acc[1], acc[2], acc[3]};
        float4 v1 = {acc[4], acc[5], acc[6], acc[7]};
        float* o = O + (size_t)wid * 256 + lane * 8;
        *(float4*)o = v0;
        *(float4*)(o + 4) = v1;
    } else {  // WID == 64: lane owns 2 columns
        float2 acc = {0, 0};
        int i = s;
        for (; i + 4 <= e; i += 4) {
            int s0 = g_csr_src[i], s1 = g_csr_src[i + 1];
            int s2 = g_csr_src[i + 2], s3 = g_csr_src[i + 3];
            float w0 = g_csr_w[i], w1 = g_csr_w[i + 1];
            float w2 = g_csr_w[i + 2], w3 = g_csr_w[i + 3];
            __half2 h0 = *(const __half2*)(S + (size_t)s0 * 64 + lane * 2);
            __half2 h1 = *(const __half2*)(S + (size_t)s1 * 64 + lane * 2);
            __half2 h2 = *(const __half2*)(S + (size_t)s2 * 64 + lane * 2);
            __half2 h3 = *(const __half2*)(S + (size_t)s3 * 64 + lane * 2);
            float2 f0 = __half22float2(h0), f1 = __half22float2(h1);
            float2 f2 = __half22float2(h2), f3 = __half22float2(h3);
            acc.x = fmaf(w0, f0.x, acc.x); acc.y = fmaf(w0, f0.y, acc.y);
            acc.x = fmaf(w1, f1.x, acc.x); acc.y = fmaf(w1, f1.y, acc.y);
            acc.x = fmaf(w2, f2.x, acc.x); acc.y = fmaf(w2, f2.y, acc.y);
            acc.x = fmaf(w3, f3.x, acc.x); acc.y = fmaf(w3, f3.y, acc.y);
        }
        for (; i < e; i++) {
            int s0 = g_csr_src[i];
            float w0 = g_csr_w[i];
            float2 f0 = __half22float2(*(const __half2*)(S + (size_t)s0 * 64 + lane * 2));
            acc.x = fmaf(w0, f0.x, acc.x); acc.y = fmaf(w0, f0.y, acc.y);
        }
        float2 b = *(const float2*)(bias + lane * 2);
        acc.x += b.x; acc.y += b.y;
        if (relu) { acc.x = fmaxf(acc.x, 0.f); acc.y = fmaxf(acc.y, 0.f); }
        *(float2*)(O + (size_t)wid * 64 + lane * 2) = acc;
    }
}

// ---------------- launch ----------------
extern "C" void kernel_launch(void* const* d_in, const int* in_sizes, int n_in,
                              void* d_out, int out_size) {
    const float* x    = (const float*)d_in[0];
    const int*   esrc = (const int*)d_in[1];
    const int*   edst = (const int*)d_in[2];
    const float* ew   = (const float*)d_in[3];
    const int*   lab  = (const int*)d_in[4];
    const float* W1   = (const float*)d_in[5];
    const float* b1   = (const float*)d_in[6];
    const float* W2   = (const float*)d_in[7];
    const float* b2   = (const float*)d_in[8];
    const float* W3   = (const float*)d_in[9];
    const float* b3   = (const float*)d_in[10];
    float* out = (float*)d_out;

    int N = in_sizes[4];
    int E = in_sizes[1];

    void *p_cnt, *p_labcnt, *p_bufA, *p_bufB, *p_bufH;
    cudaGetSymbolAddress(&p_cnt, g_cnt);
    cudaGetSymbolAddress(&p_labcnt, g_lab_cnt);
    cudaGetSymbolAddress(&p_bufA, g_bufA);
    cudaGetSymbolAddress(&p_bufB, g_bufB);
    cudaGetSymbolAddress(&p_bufH, g_bufH);
    float*  bufA = (float*)p_bufA;
    float*  bufB = (float*)p_bufB;
    __half* bufH = (__half*)p_bufH;

    static cudaStream_t s2 = nullptr;
    static cudaEvent_t evFork = nullptr, evJoin = nullptr;
    if (s2 == nullptr) {
        cudaStreamCreateWithFlags(&s2, cudaStreamNonBlocking);
        cudaEventCreateWithFlags(&evFork, cudaEventDisableTiming);
        cudaEventCreateWithFlags(&evJoin, cudaEventDisableTiming);
    }

    const int tpb = 256;

    // ---- fork: edge/CSR build on s2, label grouping + GEMM1 on main ----
    cudaEventRecord(evFork, 0);
    cudaStreamWaitEvent(s2, evFork, 0);

    cudaMemsetAsync(p_cnt, 0, (size_t)N * sizeof(int), s2);
    k_hist_edges<<<1024, tpb, 0, s2>>>(edst, E);
    k_scan_rows<<<1, 1024, 0, s2>>>(N);
    k_scatter_edges<<<1024, tpb, 0, s2>>>(esrc, edst, ew, E);
    cudaEventRecord(evJoin, s2);

    cudaMemsetAsync(p_labcnt, 0, 4 * sizeof(int), 0);
    k_hist_labels<<<128, tpb>>>(lab, N);
    k_scan_labels<<<1, 32>>>();
    k_scatter_perm<<<(N + tpb - 1) / tpb, tpb>>>(lab, N);

    int rt = (N + 127) / 128 + 4;
    int spmm_blocks = (N * 32 + tpb - 1) / tpb;

    // layer 1 dense (independent of CSR)
    k_gemm<128, 8><<<dim3(rt, 2), 256>>>(x, W1, bufH, 256, 256);

    cudaStreamWaitEvent(0, evJoin, 0);

    k_spmm<256><<<spmm_blocks, tpb>>>(bufH, bufB, b1, N, 1);
    // layer 2
    k_gemm<128, 8><<<dim3(rt, 2), 256>>>(bufB, W2, bufH, 256, 256);
    k_spmm<256><<<spmm_blocks, tpb>>>(bufH, bufA, b2, N, 1);
    // layer 3
    k_gemm<64, 4><<<dim3(rt, 1), 256>>>(bufA, W3, bufH, 256, 64);
    k_spmm<64><<<spmm_blocks, tpb>>>(bufH, out, b3, N, 0);
}

// round 5
// speedup vs baseline: 1.9889x; 1.3640x over previous
#include <cuda_runtime.h>
#include <cuda_fp16.h>
#include <cuda_bf16.h>
#include <cstdint>

#define NMAX 50048
#define EMAX 1600000

// ---------------- scratch (static device globals; no allocation) ----------------
__device__ float  g_bufA[(size_t)NMAX * 256];   // fp32 node features (ping)
__device__ float  g_bufB[(size_t)NMAX * 256];   // fp32 node features (pong)
__device__ __half g_bufH[(size_t)NMAX * 256];   // fp16 support (GEMM out / SpMM in)
__device__ int    g_csr_src[EMAX];
__device__ float  g_csr_w[EMAX];
__device__ int    g_cnt[NMAX];
__device__ int    g_row_ptr[NMAX + 1];
__device__ int    g_perm[NMAX];
__device__ int    g_lab_cnt[4];
__device__ int    g_lab_off[5];
__device__ int    g_lab_cur[4];
// pre-split bf16 weights, same [4][K][NOUT] layout as source
__device__ __nv_bfloat16 g_W1hi[4 * 256 * 256];
__device__ __nv_bfloat16 g_W1lo[4 * 256 * 256];
__device__ __nv_bfloat16 g_W2hi[4 * 256 * 256];
__device__ __nv_bfloat16 g_W2lo[4 * 256 * 256];
__device__ __nv_bfloat16 g_W3hi[4 * 256 * 64];
__device__ __nv_bfloat16 g_W3lo[4 * 256 * 64];

// ---------------- mma / ldmatrix helpers (sm_80-era PTX, valid on compute_103) ----
__device__ __forceinline__ void ldsm_x4(uint32_t* r, uint32_t addr) {
    asm volatile("ldmatrix.sync.aligned.m8n8.x4.shared.b16 {%0,%1,%2,%3}, [%4];"
                 : "=r"(r[0]), "=r"(r[1]), "=r"(r[2]), "=r"(r[3]) : "r"(addr));
}
__device__ __forceinline__ void ldsm_x2t(uint32_t* r, uint32_t addr) {
    asm volatile("ldmatrix.sync.aligned.m8n8.x2.trans.shared.b16 {%0,%1}, [%2];"
                 : "=r"(r[0]), "=r"(r[1]) : "r"(addr));
}
__device__ __forceinline__ void mma_bf16(float* c, const uint32_t* a, const uint32_t* b) {
    asm volatile(
        "mma.sync.aligned.m16n8k16.row.col.f32.bf16.bf16.f32 "
        "{%0,%1,%2,%3}, {%4,%5,%6,%7}, {%8,%9}, {%0,%1,%2,%3};"
        : "+f"(c[0]), "+f"(c[1]), "+f"(c[2]), "+f"(c[3])
        : "r"(a[0]), "r"(a[1]), "r"(a[2]), "r"(a[3]), "r"(b[0]), "r"(b[1]));
}
__device__ __forceinline__ uint32_t pack_bf2(float a, float b) {
    __nv_bfloat162 t = __floats2bfloat162_rn(a, b);
    return *reinterpret_cast<uint32_t*>(&t);
}

// ---------------- CSR / grouping build ----------------
__global__ void k_hist_edges(const int* __restrict__ dst, int E) {
    int i = blockIdx.x * blockDim.x + threadIdx.x;
    int stride = gridDim.x * blockDim.x;
    for (; i < E; i += stride) atomicAdd(&g_cnt[dst[i]], 1);
}

__global__ void k_hist_labels(const int* __restrict__ lab, int N) {
    __shared__ int c[4];
    if (threadIdx.x < 4) c[threadIdx.x] = 0;
    __syncthreads();
    int i = blockIdx.x * blockDim.x + threadIdx.x;
    int stride = gridDim.x * blockDim.x;
    for (; i < N; i += stride) atomicAdd(&c[lab[i]], 1);
    __syncthreads();
    if (threadIdx.x < 4 && c[threadIdx.x]) atomicAdd(&g_lab_cnt[threadIdx.x], c[threadIdx.x]);
}

__global__ void k_scan_rows(int N) {
    int tid = threadIdx.x;
    int chunk = (N + 1023) / 1024;
    int b = tid * chunk;
    int e = b + chunk; if (e > N) e = N;
    int s = 0;
    for (int i = b; i < e; i++) s += g_cnt[i];

    __shared__ int sm[1024];
    sm[tid] = s;
    __syncthreads();
    for (int d = 1; d < 1024; d <<= 1) {
        int v = (tid >= d) ? sm[tid - d] : 0;
        __syncthreads();
        sm[tid] += v;
        __syncthreads();
    }
    int run = sm[tid] - s;
    for (int i = b; i < e; i++) {
        int c = g_cnt[i];
        g_row_ptr[i] = run;
        g_cnt[i] = run;
        run += c;
    }
    if (tid == 1023) g_row_ptr[N] = sm[1023];
}

__global__ void k_scan_labels() {
    if (threadIdx.x == 0) {
        int o = 0;
        for (int i = 0; i < 4; i++) { g_lab_off[i] = o; g_lab_cur[i] = o; o += g_lab_cnt[i]; }
        g_lab_off[4] = o;
    }
}

__global__ void k_scatter_perm(const int* __restrict__ lab, int N) {
    __shared__ int c[4], base[4];
    if (threadIdx.x < 4) c[threadIdx.x] = 0;
    __syncthreads();
    int i = blockIdx.x * blockDim.x + threadIdx.x;
    int l = 0, local = 0;
    bool valid = (i < N);
    if (valid) {
        l = lab[i];
        local = atomicAdd(&c[l], 1);
    }
    __syncthreads();
    if (threadIdx.x < 4)
        base[threadIdx.x] = c[threadIdx.x] ? atomicAdd(&g_lab_cur[threadIdx.x], c[threadIdx.x]) : 0;
    __syncthreads();
    if (valid) g_perm[base[l] + local] = i;
}

__global__ void k_scatter_edges(const int* __restrict__ src, const int* __restrict__ dst,
                                const float* __restrict__ w, int E) {
    int i = blockIdx.x * blockDim.x + threadIdx.x;
    int stride = gridDim.x * blockDim.x;
    for (; i < E; i += stride) {
        int p = atomicAdd(&g_cnt[dst[i]], 1);
        g_csr_src[p] = src[i];
        g_csr_w[p] = w[i];
    }
}

// ---------------- weight split: fp32 -> bf16 hi/lo (elementwise) ----------------
__global__ void k_wsplit(const float* __restrict__ W, __nv_bfloat16* __restrict__ Whi,
                         __nv_bfloat16* __restrict__ Wlo, int n) {
    int i = blockIdx.x * blockDim.x + threadIdx.x;
    int stride = gridDim.x * blockDim.x;
    for (; i < n; i += stride) {
        float v = W[i];
        __nv_bfloat16 h = __float2bfloat16(v);
        Whi[i] = h;
        Wlo[i] = __float2bfloat16(v - __bfloat162float(h));
    }
}

// ---------------- tensor-core grouped dense: H = fp16( X @ W[label] ) ----------------
// BM=128, BK=32, 256 threads (8 warps). Split bf16: hi*hi + hi*lo + lo*hi, fp32 acc.
template <int BN>
__global__ void __launch_bounds__(256, 1)
k_gemm_mma(const float* __restrict__ X,
           const __nv_bfloat16* __restrict__ Whi,
           const __nv_bfloat16* __restrict__ Wlo,
           __half* __restrict__ S, int NOUT) {
    constexpr int BM = 128, BK = 32, K = 256;
    constexpr int WR_N = (BN == 128) ? 4 : 2;
    constexpr int WM = (BN == 128) ? 64 : 32;      // warp M tile
    constexpr int WN = 32;                          // warp N tile
    constexpr int M_TILES = WM / 16;                // 4 or 2
    constexpr int N_TILES = WN / 8;                 // 4
    constexpr int AS = 40;                          // A smem stride (bf16)
    constexpr int BS = BN + 8;                      // B smem stride (bf16)
    constexpr int ASZ = BM * AS;                    // per A buffer (elems)
    constexpr int BSZ = BK * BS;

    __shared__ __align__(16) __nv_bfloat16 sA[2 * ASZ];  // hi | lo
    __shared__ __align__(16) __nv_bfloat16 sB[2 * BSZ];
    __shared__ int snode[BM];

    int tid = threadIdx.x;
    int w = tid >> 5, lane = tid & 31;
    int wm = w / WR_N, wn = w % WR_N;
    int warp_m0 = wm * WM, warp_n0 = wn * WN;

    // --- group / tile mapping ---
    int bx = blockIdx.x;
    int c0 = g_lab_cnt[0], c1 = g_lab_cnt[1], c2 = g_lab_cnt[2], c3 = g_lab_cnt[3];
    int t0 = (c0 + BM - 1) / BM, t1 = (c1 + BM - 1) / BM,
        t2 = (c2 + BM - 1) / BM, t3 = (c3 + BM - 1) / BM;
    int g, tile;
    if      (bx < t0)                { g = 0; tile = bx; }
    else if (bx < t0 + t1)           { g = 1; tile = bx - t0; }
    else if (bx < t0 + t1 + t2)      { g = 2; tile = bx - t0 - t1; }
    else if (bx < t0 + t1 + t2 + t3) { g = 3; tile = bx - t0 - t1 - t2; }
    else return;
    int cnt = g_lab_cnt[g];
    int off = g_lab_off[g];

    if (tid < BM) {
        int idx = tile * BM + tid;
        snode[tid] = (idx < cnt) ? g_perm[off + idx] : -1;
    }
    __syncthreads();

    const __nv_bfloat16* WhiG = Whi + (size_t)g * K * NOUT + blockIdx.y * BN;
    const __nv_bfloat16* WloG = Wlo + (size_t)g * K * NOUT + blockIdx.y * BN;

    // A loader: 2 threads per row, each 16 consecutive floats
    int arow = tid >> 1, ahalf = tid & 1;
    int anode = snode[arow]; if (anode < 0) anode = 0;
    const float* aptr = X + (size_t)anode * K + ahalf * 16;

    // B loader: row = tid>>3, colgrp = tid&7, BN/8 bf16 per thread
    int brow = tid >> 3, bcolg = tid & 7;
    constexpr int BPT = BN / 8;  // 16 or 8 bf16 per thread

    uint32_t sA_u = (uint32_t)__cvta_generic_to_shared(sA);
    uint32_t sB_u = (uint32_t)__cvta_generic_to_shared(sB);

    // ldmatrix lane addressing (precompute lane-dependent parts)
    int a_m = lane & 15, a_koff = (lane >> 4) * 8;
    int b_k = lane & 15;

    float acc[M_TILES][N_TILES][4];
#pragma unroll
    for (int i = 0; i < M_TILES; i++)
#pragma unroll
        for (int j = 0; j < N_TILES; j++)
#pragma unroll
            for (int q = 0; q < 4; q++) acc[i][j][q] = 0.0f;

    for (int kc = 0; kc < K; kc += BK) {
        // ---- global loads (before sync: hide behind previous MMAs)
        float4 av0 = *(const float4*)(aptr + kc);
        float4 av1 = *(const float4*)(aptr + kc + 4);
        float4 av2 = *(const float4*)(aptr + kc + 8);
        float4 av3 = *(const float4*)(aptr + kc + 12);
        uint4 bh0, bh1, bl0, bl1;
        {
            const __nv_bfloat16* ph = WhiG + (size_t)(kc + brow) * NOUT + bcolg * BPT;
            const __nv_bfloat16* pl = WloG + (size_t)(kc + brow) * NOUT + bcolg * BPT;
            bh0 = *(const uint4*)ph;
            bl0 = *(const uint4*)pl;
            if (BPT == 16) {
                bh1 = *(const uint4*)(ph + 8);
                bl1 = *(const uint4*)(pl + 8);
            }
        }

        __syncthreads();  // previous chunk's MMAs done with smem

        // ---- convert + store A (hi/lo)
        {
            float f[16] = {av0.x, av0.y, av0.z, av0.w, av1.x, av1.y, av1.z, av1.w,
                           av2.x, av2.y, av2.z, av2.w, av3.x, av3.y, av3.z, av3.w};
            uint32_t hp[8], lp[8];
#pragma unroll
            for (int q = 0; q < 8; q++) {
                float x0 = f[q * 2], x1 = f[q * 2 + 1];
                __nv_bfloat16 h0 = __float2bfloat16(x0);
                __nv_bfloat16 h1 = __float2bfloat16(x1);
                hp[q] = pack_bf2(x0, x1);  // rn pack of hi values
                lp[q] = pack_bf2(x0 - __bfloat162float(h0), x1 - __bfloat162float(h1));
            }
            __nv_bfloat16* dh = sA + arow * AS + ahalf * 16;
            __nv_bfloat16* dl = dh + ASZ;
            ((uint4*)dh)[0] = make_uint4(hp[0], hp[1], hp[2], hp[3]);
            ((uint4*)dh)[1] = make_uint4(hp[4], hp[5], hp[6], hp[7]);
            ((uint4*)dl)[0] = make_uint4(lp[0], lp[1], lp[2], lp[3]);
            ((uint4*)dl)[1] = make_uint4(lp[4], lp[5], lp[6], lp[7]);
        }
        // ---- store B (hi/lo)
        {
            __nv_bfloat16* dh = sB + brow * BS + bcolg * BPT;
            __nv_bfloat16* dl = dh + BSZ;
            ((uint4*)dh)[0] = bh0;
            ((uint4*)dl)[0] = bl0;
            if (BPT == 16) {
                ((uint4*)dh)[1] = bh1;
                ((uint4*)dl)[1] = bl1;
            }
        }
        __syncthreads();

        // ---- MMAs: 2 k-steps of 16
#pragma unroll
        for (int ks = 0; ks < 2; ks++) {
            uint32_t afh[M_TILES][4], afl[M_TILES][4];
            uint32_t bfh[N_TILES][2], bfl[N_TILES][2];
#pragma unroll
            for (int mt = 0; mt < M_TILES; mt++) {
                uint32_t ra = sA_u + ((warp_m0 + mt * 16 + a_m) * AS + ks * 16 + a_koff) * 2;
                ldsm_x4(afh[mt], ra);
                ldsm_x4(afl[mt], ra + ASZ * 2);
            }
#pragma unroll
            for (int nt = 0; nt < N_TILES; nt++) {
                uint32_t rb = sB_u + ((ks * 16 + b_k) * BS + warp_n0 + nt * 8) * 2;
                ldsm_x2t(bfh[nt], rb);
                ldsm_x2t(bfl[nt], rb + BSZ * 2);
            }
#pragma unroll
            for (int mt = 0; mt < M_TILES; mt++)
#pragma unroll
                for (int nt = 0; nt < N_TILES; nt++) {
                    mma_bf16(acc[mt][nt], afh[mt], bfh[nt]);
                    mma_bf16(acc[mt][nt], afh[mt], bfl[nt]);
                    mma_bf16(acc[mt][nt], afl[mt], bfh[nt]);
                }
        }
    }

    // ---- epilogue: fp16 scattered rows
    int grow = lane >> 2, gcol = (lane & 3) * 2;
#pragma unroll
    for (int mt = 0; mt < M_TILES; mt++) {
        int m1 = warp_m0 + mt * 16 + grow;
        int m2 = m1 + 8;
        int n1 = snode[m1], n2 = snode[m2];
#pragma unroll
        for (int nt = 0; nt < N_TILES; nt++) {
            int col = blockIdx.y * BN + warp_n0 + nt * 8 + gcol;
            if (n1 >= 0)
                *(__half2*)(S + (size_t)n1 * NOUT + col) =
                    __floats2half2_rn(acc[mt][nt][0], acc[mt][nt][1]);
            if (n2 >= 0)
                *(__half2*)(S + (size_t)n2 * NOUT + col) =
                    __floats2half2_rn(acc[mt][nt][2], acc[mt][nt][3]);
        }
    }
}

// ---------------- sparse aggregation (gather by dst, CSR, fp16 support) ----------------
template <int WID>
__global__ void __launch_bounds__(256)
k_spmm(const __half* __restrict__ S, float* __restrict__ O,
       const float* __restrict__ bias, int N, int relu) {
    int wid = (blockIdx.x * blockDim.x + threadIdx.x) >> 5;
    int lane = threadIdx.x & 31;
    if (wid >= N) return;
    int s = g_row_ptr[wid], e = g_row_ptr[wid + 1];

    if (WID == 256) {
        float acc[8];
#pragma unroll
        for (int q = 0; q < 8; q++) acc[q] = 0.0f;

        int i = s;
        for (; i + 4 <= e; i += 4) {
            int s0 = g_csr_src[i], s1 = g_csr_src[i + 1];
            int s2 = g_csr_src[i + 2], s3 = g_csr_src[i + 3];
            float w0 = g_csr_w[i], w1 = g_csr_w[i + 1];
            float w2 = g_csr_w[i + 2], w3 = g_csr_w[i + 3];
            uint4 q0 = *(const uint4*)(S + (size_t)s0 * 256 + lane * 8);
            uint4 q1 = *(const uint4*)(S + (size_t)s1 * 256 + lane * 8);
            uint4 q2 = *(const uint4*)(S + (size_t)s2 * 256 + lane * 8);
            uint4 q3 = *(const uint4*)(S + (size_t)s3 * 256 + lane * 8);
#pragma unroll
            for (int h = 0; h < 4; h++) {
                float2 f0 = __half22float2(((const __half2*)&q0)[h]);
                float2 f1 = __half22float2(((const __half2*)&q1)[h]);
                float2 f2 = __half22float2(((const __half2*)&q2)[h]);
                float2 f3 = __half22float2(((const __half2*)&q3)[h]);
                acc[h * 2 + 0] = fmaf(w0, f0.x, acc[h * 2 + 0]);
                acc[h * 2 + 1] = fmaf(w0, f0.y, acc[h * 2 + 1]);
                acc[h * 2 + 0] = fmaf(w1, f1.x, acc[h * 2 + 0]);
                acc[h * 2 + 1] = fmaf(w1, f1.y, acc[h * 2 + 1]);
                acc[h * 2 + 0] = fmaf(w2, f2.x, acc[h * 2 + 0]);
                acc[h * 2 + 1] = fmaf(w2, f2.y, acc[h * 2 + 1]);
                acc[h * 2 + 0] = fmaf(w3, f3.x, acc[h * 2 + 0]);
                acc[h * 2 + 1] = fmaf(w3, f3.y, acc[h * 2 + 1]);
            }
        }
        for (; i < e; i++) {
            int s0 = g_csr_src[i];
            float w0 = g_csr_w[i];
            uint4 q0 = *(const uint4*)(S + (size_t)s0 * 256 + lane * 8);
#pragma unroll
            for (int h = 0; h < 4; h++) {
                float2 f0 = __half22float2(((const __half2*)&q0)[h]);
                acc[h * 2 + 0] = fmaf(w0, f0.x, acc[h * 2 + 0]);
                acc[h * 2 + 1] = fmaf(w0, f0.y, acc[h * 2 + 1]);
            }
        }
        float4 b0 = *(const float4*)(bias + lane * 8);
        float4 b1 = *(const float4*)(bias + lane * 8 + 4);
        acc[0] += b0.x; acc[1] += b0.y; acc[2] += b0.z; acc[3] += b0.w;
        acc[4] += b1.x; acc[5] += b1.y; acc[6] += b1.z; acc[7] += b1.w;
        if (relu) {
#pragma unroll
            for (int q = 0; q < 8; q++) acc[q] = fmaxf(acc[q], 0.0f);
        }
        float4 v0 = {acc[0], acc[1], acc[2], acc[3]};
        float4 v1 = {acc[4], acc[5], acc[6], acc[7]};
        float* o = O + (size_t)wid * 256 + lane * 8;
        *(float4*)o = v0;
        *(float4*)(o + 4) = v1;
    } else {  // WID == 64
        float2 acc = {0, 0};
        int i = s;
        for (; i + 4 <= e; i += 4) {
            int s0 = g_csr_src[i], s1 = g_csr_src[i + 1];
            int s2 = g_csr_src[i + 2], s3 = g_csr_src[i + 3];
            float w0 = g_csr_w[i], w1 = g_csr_w[i + 1];
            float w2 = g_csr_w[i + 2], w3 = g_csr_w[i + 3];
            __half2 h0 = *(const __half2*)(S + (size_t)s0 * 64 + lane * 2);
            __half2 h1 = *(const __half2*)(S + (size_t)s1 * 64 + lane * 2);
            __half2 h2 = *(const __half2*)(S + (size_t)s2 * 64 + lane * 2);
            __half2 h3 = *(const __half2*)(S + (size_t)s3 * 64 + lane * 2);
            float2 f0 = __half22float2(h0), f1 = __half22float2(h1);
            float2 f2 = __half22float2(h2), f3 = __half22float2(h3);
            acc.x = fmaf(w0, f0.x, acc.x); acc.y = fmaf(w0, f0.y, acc.y);
            acc.x = fmaf(w1, f1.x, acc.x); acc.y = fmaf(w1, f1.y, acc.y);
            acc.x = fmaf(w2, f2.x, acc.x); acc.y = fmaf(w2, f2.y, acc.y);
            acc.x = fmaf(w3, f3.x, acc.x); acc.y = fmaf(w3, f3.y, acc.y);
        }
        for (; i < e; i++) {
            int s0 = g_csr_src[i];
            float w0 = g_csr_w[i];
            float2 f0 = __half22float2(*(const __half2*)(S + (size_t)s0 * 64 + lane * 2));
            acc.x = fmaf(w0, f0.x, acc.x); acc.y = fmaf(w0, f0.y, acc.y);
        }
        float2 b = *(const float2*)(bias + lane * 2);
        acc.x += b.x; acc.y += b.y;
        if (relu) { acc.x = fmaxf(acc.x, 0.f); acc.y = fmaxf(acc.y, 0.f); }
        *(float2*)(O + (size_t)wid * 64 + lane * 2) = acc;
    }
}

// ---------------- launch ----------------
extern "C" void kernel_launch(void* const* d_in, const int* in_sizes, int n_in,
                              void* d_out, int out_size) {
    const float* x    = (const float*)d_in[0];
    const int*   esrc = (const int*)d_in[1];
    const int*   edst = (const int*)d_in[2];
    const float* ew   = (const float*)d_in[3];
    const int*   lab  = (const int*)d_in[4];
    const float* W1   = (const float*)d_in[5];
    const float* b1   = (const float*)d_in[6];
    const float* W2   = (const float*)d_in[7];
    const float* b2   = (const float*)d_in[8];
    const float* W3   = (const float*)d_in[9];
    const float* b3   = (const float*)d_in[10];
    float* out = (float*)d_out;

    int N = in_sizes[4];
    int E = in_sizes[1];

    void *p_cnt, *p_labcnt, *p_bufA, *p_bufB, *p_bufH;
    void *p_w1h, *p_w1l, *p_w2h, *p_w2l, *p_w3h, *p_w3l;
    cudaGetSymbolAddress(&p_cnt, g_cnt);
    cudaGetSymbolAddress(&p_labcnt, g_lab_cnt);
    cudaGetSymbolAddress(&p_bufA, g_bufA);
    cudaGetSymbolAddress(&p_bufB, g_bufB);
    cudaGetSymbolAddress(&p_bufH, g_bufH);
    cudaGetSymbolAddress(&p_w1h, g_W1hi); cudaGetSymbolAddress(&p_w1l, g_W1lo);
    cudaGetSymbolAddress(&p_w2h, g_W2hi); cudaGetSymbolAddress(&p_w2l, g_W2lo);
    cudaGetSymbolAddress(&p_w3h, g_W3hi); cudaGetSymbolAddress(&p_w3l, g_W3lo);
    float*  bufA = (float*)p_bufA;
    float*  bufB = (float*)p_bufB;
    __half* bufH = (__half*)p_bufH;

    static cudaStream_t s2 = nullptr;
    static cudaEvent_t evFork = nullptr, evJoin = nullptr;
    if (s2 == nullptr) {
        cudaStreamCreateWithFlags(&s2, cudaStreamNonBlocking);
        cudaEventCreateWithFlags(&evFork, cudaEventDisableTiming);
        cudaEventCreateWithFlags(&evJoin, cudaEventDisableTiming);
    }

    const int tpb = 256;

    // ---- fork: CSR build + W2/W3 split on s2; label grouping + W1 split + GEMM1 on main
    cudaEventRecord(evFork, 0);
    cudaStreamWaitEvent(s2, evFork, 0);

    cudaMemsetAsync(p_cnt, 0, (size_t)N * sizeof(int), s2);
    k_hist_edges<<<1024, tpb, 0, s2>>>(edst, E);
    k_scan_rows<<<1, 1024, 0, s2>>>(N);
    k_scatter_edges<<<1024, tpb, 0, s2>>>(esrc, edst, ew, E);
    k_wsplit<<<256, tpb, 0, s2>>>(W2, (__nv_bfloat16*)p_w2h, (__nv_bfloat16*)p_w2l, 4 * 256 * 256);
    k_wsplit<<<64, tpb, 0, s2>>>(W3, (__nv_bfloat16*)p_w3h, (__nv_bfloat16*)p_w3l, 4 * 256 * 64);
    cudaEventRecord(evJoin, s2);

    cudaMemsetAsync(p_labcnt, 0, 4 * sizeof(int), 0);
    k_hist_labels<<<128, tpb>>>(lab, N);
    k_scan_labels<<<1, 32>>>();
    k_scatter_perm<<<(N + tpb - 1) / tpb, tpb>>>(lab, N);
    k_wsplit<<<256, tpb>>>(W1, (__nv_bfloat16*)p_w1h, (__nv_bfloat16*)p_w1l, 4 * 256 * 256);

    int rt = (N + 127) / 128 + 4;
    int spmm_blocks = (N * 32 + tpb - 1) / tpb;

    // layer 1 dense (independent of CSR)
    k_gemm_mma<128><<<dim3(rt, 2), 256>>>(x, (const __nv_bfloat16*)p_w1h,
                                          (const __nv_bfloat16*)p_w1l, bufH, 256);

    cudaStreamWaitEvent(0, evJoin, 0);

    k_spmm<256><<<spmm_blocks, tpb>>>(bufH, bufB, b1, N, 1);
    // layer 2
    k_gemm_mma<128><<<dim3(rt, 2), 256>>>(bufB, (const __nv_bfloat16*)p_w2h,
                                          (const __nv_bfloat16*)p_w2l, bufH, 256);
    k_spmm<256><<<spmm_blocks, tpb>>>(bufH, bufA, b2, N, 1);
    // layer 3
    k_gemm_mma<64><<<dim3(rt, 1), 256>>>(bufA, (const __nv_bfloat16*)p_w3h,
                                         (const __nv_bfloat16*)p_w3l, bufH, 64);
    k_spmm<64><<<spmm_blocks, tpb>>>(bufH, out, b3, N, 0);
}

// round 6
// speedup vs baseline: 2.2396x; 1.1261x over previous
#include <cuda_runtime.h>
#include <cuda_fp16.h>
#include <cuda_bf16.h>
#include <cstdint>

#define NMAX 50048
#define EMAX 1600000

// ---------------- scratch (static device globals; no allocation) ----------------
__device__ __half g_bufH[(size_t)NMAX * 256];   // fp16 support (GEMM out / SpMM in)
__device__ __half g_bufF[(size_t)NMAX * 256];   // fp16 features (SpMM out / GEMM in)
__device__ int    g_csr_src[EMAX];
__device__ float  g_csr_w[EMAX];
__device__ int    g_cnt[NMAX];
__device__ int    g_row_ptr[NMAX + 1];
__device__ int    g_perm[NMAX];
__device__ int    g_lab_cnt[4];
__device__ int    g_lab_off[5];
__device__ int    g_lab_cur[4];
// pre-split bf16 weights, same [4][K][NOUT] layout as source
__device__ __nv_bfloat16 g_W1hi[4 * 256 * 256];
__device__ __nv_bfloat16 g_W1lo[4 * 256 * 256];
__device__ __nv_bfloat16 g_W2hi[4 * 256 * 256];
__device__ __nv_bfloat16 g_W2lo[4 * 256 * 256];
__device__ __nv_bfloat16 g_W3hi[4 * 256 * 64];
__device__ __nv_bfloat16 g_W3lo[4 * 256 * 64];

// ---------------- mma / ldmatrix helpers (sm_80-era PTX, valid on compute_103) ----
__device__ __forceinline__ void ldsm_x4(uint32_t* r, uint32_t addr) {
    asm volatile("ldmatrix.sync.aligned.m8n8.x4.shared.b16 {%0,%1,%2,%3}, [%4];"
                 : "=r"(r[0]), "=r"(r[1]), "=r"(r[2]), "=r"(r[3]) : "r"(addr));
}
__device__ __forceinline__ void ldsm_x2t(uint32_t* r, uint32_t addr) {
    asm volatile("ldmatrix.sync.aligned.m8n8.x2.trans.shared.b16 {%0,%1}, [%2];"
                 : "=r"(r[0]), "=r"(r[1]) : "r"(addr));
}
__device__ __forceinline__ void mma_bf16(float* c, const uint32_t* a, const uint32_t* b) {
    asm volatile(
        "mma.sync.aligned.m16n8k16.row.col.f32.bf16.bf16.f32 "
        "{%0,%1,%2,%3}, {%4,%5,%6,%7}, {%8,%9}, {%0,%1,%2,%3};"
        : "+f"(c[0]), "+f"(c[1]), "+f"(c[2]), "+f"(c[3])
        : "r"(a[0]), "r"(a[1]), "r"(a[2]), "r"(a[3]), "r"(b[0]), "r"(b[1]));
}
__device__ __forceinline__ uint32_t pack_bf2(float a, float b) {
    __nv_bfloat162 t = __floats2bfloat162_rn(a, b);
    return *reinterpret_cast<uint32_t*>(&t);
}
__device__ __forceinline__ uint32_t h2u(__half2 h) { return *reinterpret_cast<uint32_t*>(&h); }

// ---------------- CSR / grouping build ----------------
__global__ void k_hist_edges(const int* __restrict__ dst, int E) {
    int i = blockIdx.x * blockDim.x + threadIdx.x;
    int stride = gridDim.x * blockDim.x;
    for (; i < E; i += stride) atomicAdd(&g_cnt[dst[i]], 1);
}

__global__ void k_hist_labels(const int* __restrict__ lab, int N) {
    __shared__ int c[4];
    if (threadIdx.x < 4) c[threadIdx.x] = 0;
    __syncthreads();
    int i = blockIdx.x * blockDim.x + threadIdx.x;
    int stride = gridDim.x * blockDim.x;
    for (; i < N; i += stride) atomicAdd(&c[lab[i]], 1);
    __syncthreads();
    if (threadIdx.x < 4 && c[threadIdx.x]) atomicAdd(&g_lab_cnt[threadIdx.x], c[threadIdx.x]);
}

__global__ void k_scan_rows(int N) {
    int tid = threadIdx.x;
    int chunk = (N + 1023) / 1024;
    int b = tid * chunk;
    int e = b + chunk; if (e > N) e = N;
    int s = 0;
    for (int i = b; i < e; i++) s += g_cnt[i];

    __shared__ int sm[1024];
    sm[tid] = s;
    __syncthreads();
    for (int d = 1; d < 1024; d <<= 1) {
        int v = (tid >= d) ? sm[tid - d] : 0;
        __syncthreads();
        sm[tid] += v;
        __syncthreads();
    }
    int run = sm[tid] - s;
    for (int i = b; i < e; i++) {
        int c = g_cnt[i];
        g_row_ptr[i] = run;
        g_cnt[i] = run;
        run += c;
    }
    if (tid == 1023) g_row_ptr[N] = sm[1023];
}

__global__ void k_scan_labels() {
    if (threadIdx.x == 0) {
        int o = 0;
        for (int i = 0; i < 4; i++) { g_lab_off[i] = o; g_lab_cur[i] = o; o += g_lab_cnt[i]; }
        g_lab_off[4] = o;
    }
}

__global__ void k_scatter_perm(const int* __restrict__ lab, int N) {
    __shared__ int c[4], base[4];
    if (threadIdx.x < 4) c[threadIdx.x] = 0;
    __syncthreads();
    int i = blockIdx.x * blockDim.x + threadIdx.x;
    int l = 0, local = 0;
    bool valid = (i < N);
    if (valid) {
        l = lab[i];
        local = atomicAdd(&c[l], 1);
    }
    __syncthreads();
    if (threadIdx.x < 4)
        base[threadIdx.x] = c[threadIdx.x] ? atomicAdd(&g_lab_cur[threadIdx.x], c[threadIdx.x]) : 0;
    __syncthreads();
    if (valid) g_perm[base[l] + local] = i;
}

__global__ void k_scatter_edges(const int* __restrict__ src, const int* __restrict__ dst,
                                const float* __restrict__ w, int E) {
    int i = blockIdx.x * blockDim.x + threadIdx.x;
    int stride = gridDim.x * blockDim.x;
    for (; i < E; i += stride) {
        int p = atomicAdd(&g_cnt[dst[i]], 1);
        g_csr_src[p] = src[i];
        g_csr_w[p] = w[i];
    }
}

// ---------------- weight split: fp32 -> bf16 hi/lo (elementwise) ----------------
__global__ void k_wsplit(const float* __restrict__ W, __nv_bfloat16* __restrict__ Whi,
                         __nv_bfloat16* __restrict__ Wlo, int n) {
    int i = blockIdx.x * blockDim.x + threadIdx.x;
    int stride = gridDim.x * blockDim.x;
    for (; i < n; i += stride) {
        float v = W[i];
        __nv_bfloat16 h = __float2bfloat16(v);
        Whi[i] = h;
        Wlo[i] = __float2bfloat16(v - __bfloat162float(h));
    }
}

// ---------------- tensor-core grouped dense: H = fp16( X @ W[label] ) ----------------
// BM=128, BK=32, 256 threads (8 warps). Split bf16: hi*hi + hi*lo + lo*hi, fp32 acc.
// Double-buffered smem, one __syncthreads per K-chunk. TIN = float or __half.
template <int BN, typename TIN>
__global__ void __launch_bounds__(256, 1)
k_gemm_mma(const TIN* __restrict__ X,
           const __nv_bfloat16* __restrict__ Whi,
           const __nv_bfloat16* __restrict__ Wlo,
           __half* __restrict__ S, int NOUT) {
    constexpr int BM = 128, BK = 32, K = 256, CHUNKS = K / BK;
    constexpr int WR_N = (BN == 128) ? 4 : 2;
    constexpr int WM = (BN == 128) ? 64 : 32;
    constexpr int WN = 32;
    constexpr int M_TILES = WM / 16;
    constexpr int N_TILES = WN / 8;
    constexpr int AS = 40;                       // A smem stride (bf16)
    constexpr int BS = BN + 8;                   // B smem stride (bf16)
    constexpr int ASZ = BM * AS;                 // one A plane (elems)
    constexpr int BSZ = BK * BS;                 // one B plane (elems)
    constexpr bool IN32 = (sizeof(TIN) == 4);

    extern __shared__ __align__(16) __nv_bfloat16 dyn[];
    // layout: A: buf*(2*ASZ) + plane*ASZ   |  B at 4*ASZ: buf*(2*BSZ) + plane*BSZ
    __shared__ int snode[BM];

    int tid = threadIdx.x;
    int w = tid >> 5, lane = tid & 31;
    int wm = w / WR_N, wn = w % WR_N;
    int warp_m0 = wm * WM, warp_n0 = wn * WN;

    // --- group / tile mapping ---
    int bx = blockIdx.x;
    int c0 = g_lab_cnt[0], c1 = g_lab_cnt[1], c2 = g_lab_cnt[2], c3 = g_lab_cnt[3];
    int t0 = (c0 + BM - 1) / BM, t1 = (c1 + BM - 1) / BM,
        t2 = (c2 + BM - 1) / BM, t3 = (c3 + BM - 1) / BM;
    int g, tile;
    if      (bx < t0)                { g = 0; tile = bx; }
    else if (bx < t0 + t1)           { g = 1; tile = bx - t0; }
    else if (bx < t0 + t1 + t2)      { g = 2; tile = bx - t0 - t1; }
    else if (bx < t0 + t1 + t2 + t3) { g = 3; tile = bx - t0 - t1 - t2; }
    else return;
    int cnt = g_lab_cnt[g];
    int off = g_lab_off[g];

    if (tid < BM) {
        int idx = tile * BM + tid;
        snode[tid] = (idx < cnt) ? g_perm[off + idx] : -1;
    }
    __syncthreads();

    const __nv_bfloat16* WhiG = Whi + (size_t)g * K * NOUT + blockIdx.y * BN;
    const __nv_bfloat16* WloG = Wlo + (size_t)g * K * NOUT + blockIdx.y * BN;

    // A loader: 2 threads per row, each 16 consecutive k-values
    int arow = tid >> 1, ahalf = tid & 1;
    int anode = snode[arow]; if (anode < 0) anode = 0;
    const TIN* aptr = X + (size_t)anode * K + ahalf * 16;

    // B loader
    int brow = tid >> 3, bcolg = tid & 7;
    constexpr int BPT = BN / 8;  // 16 or 8 bf16 per thread

    uint32_t dyn_u = (uint32_t)__cvta_generic_to_shared(dyn);

    int a_m = lane & 15, a_koff = (lane >> 4) * 8;
    int b_k = lane & 15;

    float acc[M_TILES][N_TILES][4];
#pragma unroll
    for (int i = 0; i < M_TILES; i++)
#pragma unroll
        for (int j = 0; j < N_TILES; j++)
#pragma unroll
            for (int q = 0; q < 4; q++) acc[i][j][q] = 0.0f;

    // prefetch registers
    float4 av32[4];
    uint4 av16[2];
    uint4 bh0, bh1, bl0, bl1;

    auto loadRegs = [&](int kc) {
        if (IN32) {
            const float* ap = (const float*)aptr + kc;
            av32[0] = *(const float4*)(ap);
            av32[1] = *(const float4*)(ap + 4);
            av32[2] = *(const float4*)(ap + 8);
            av32[3] = *(const float4*)(ap + 12);
        } else {
            const __half* ap = (const __half*)aptr + kc;
            av16[0] = *(const uint4*)(ap);
            av16[1] = *(const uint4*)(ap + 8);
        }
        const __nv_bfloat16* ph = WhiG + (size_t)(kc + brow) * NOUT + bcolg * BPT;
        const __nv_bfloat16* pl = WloG + (size_t)(kc + brow) * NOUT + bcolg * BPT;
        bh0 = *(const uint4*)ph;
        bl0 = *(const uint4*)pl;
        if (BPT == 16) {
            bh1 = *(const uint4*)(ph + 8);
            bl1 = *(const uint4*)(pl + 8);
        }
    };

    auto storeSmem = [&](int buf) {
        // A: convert fp32/fp16 -> bf16 hi/lo
        float f[16];
        if (IN32) {
            f[0] = av32[0].x; f[1] = av32[0].y; f[2] = av32[0].z; f[3] = av32[0].w;
            f[4] = av32[1].x; f[5] = av32[1].y; f[6] = av32[1].z; f[7] = av32[1].w;
            f[8] = av32[2].x; f[9] = av32[2].y; f[10] = av32[2].z; f[11] = av32[2].w;
            f[12] = av32[3].x; f[13] = av32[3].y; f[14] = av32[3].z; f[15] = av32[3].w;
        } else {
            const __half2* hp = (const __half2*)&av16[0];
#pragma unroll
            for (int q = 0; q < 4; q++) {
                float2 t = __half22float2(hp[q]);
                f[q * 2] = t.x; f[q * 2 + 1] = t.y;
            }
            hp = (const __half2*)&av16[1];
#pragma unroll
            for (int q = 0; q < 4; q++) {
                float2 t = __half22float2(hp[q]);
                f[8 + q * 2] = t.x; f[8 + q * 2 + 1] = t.y;
            }
        }
        uint32_t hp_[8], lp_[8];
#pragma unroll
        for (int q = 0; q < 8; q++) {
            float x0 = f[q * 2], x1 = f[q * 2 + 1];
            __nv_bfloat16 h0 = __float2bfloat16(x0);
            __nv_bfloat16 h1 = __float2bfloat16(x1);
            hp_[q] = pack_bf2(x0, x1);
            lp_[q] = pack_bf2(x0 - __bfloat162float(h0), x1 - __bfloat162float(h1));
        }
        __nv_bfloat16* dh = dyn + buf * (2 * ASZ) + arow * AS + ahalf * 16;
        __nv_bfloat16* dl = dh + ASZ;
        ((uint4*)dh)[0] = make_uint4(hp_[0], hp_[1], hp_[2], hp_[3]);
        ((uint4*)dh)[1] = make_uint4(hp_[4], hp_[5], hp_[6], hp_[7]);
        ((uint4*)dl)[0] = make_uint4(lp_[0], lp_[1], lp_[2], lp_[3]);
        ((uint4*)dl)[1] = make_uint4(lp_[4], lp_[5], lp_[6], lp_[7]);
        // B
        __nv_bfloat16* bh = dyn + 4 * ASZ + buf * (2 * BSZ) + brow * BS + bcolg * BPT;
        __nv_bfloat16* bl = bh + BSZ;
        ((uint4*)bh)[0] = bh0;
        ((uint4*)bl)[0] = bl0;
        if (BPT == 16) {
            ((uint4*)bh)[1] = bh1;
            ((uint4*)bl)[1] = bl1;
        }
    };

    // prologue
    loadRegs(0);
    storeSmem(0);
    __syncthreads();

    for (int kc = 0; kc < CHUNKS; kc++) {
        int cur = kc & 1;
        if (kc + 1 < CHUNKS) loadRegs((kc + 1) * BK);

        uint32_t aBase = dyn_u + (uint32_t)(cur * 2 * ASZ) * 2;
        uint32_t bBase = dyn_u + (uint32_t)(4 * ASZ + cur * 2 * BSZ) * 2;
#pragma unroll
        for (int ks = 0; ks < 2; ks++) {
            uint32_t afh[M_TILES][4], afl[M_TILES][4];
            uint32_t bfh[N_TILES][2], bfl[N_TILES][2];
#pragma unroll
            for (int mt = 0; mt < M_TILES; mt++) {
                uint32_t ra = aBase + (uint32_t)((warp_m0 + mt * 16 + a_m) * AS + ks * 16 + a_koff) * 2;
                ldsm_x4(afh[mt], ra);
                ldsm_x4(afl[mt], ra + ASZ * 2);
            }
#pragma unroll
            for (int nt = 0; nt < N_TILES; nt++) {
                uint32_t rb = bBase + (uint32_t)((ks * 16 + b_k) * BS + warp_n0 + nt * 8) * 2;
                ldsm_x2t(bfh[nt], rb);
                ldsm_x2t(bfl[nt], rb + BSZ * 2);
            }
#pragma unroll
            for (int mt = 0; mt < M_TILES; mt++)
#pragma unroll
                for (int nt = 0; nt < N_TILES; nt++) {
                    mma_bf16(acc[mt][nt], afh[mt], bfh[nt]);
                    mma_bf16(acc[mt][nt], afh[mt], bfl[nt]);
                    mma_bf16(acc[mt][nt], afl[mt], bfh[nt]);
                }
        }

        if (kc + 1 < CHUNKS) storeSmem(cur ^ 1);
        __syncthreads();
    }

    // ---- epilogue: fp16 scattered rows
    int grow = lane >> 2, gcol = (lane & 3) * 2;
#pragma unroll
    for (int mt = 0; mt < M_TILES; mt++) {
        int m1 = warp_m0 + mt * 16 + grow;
        int m2 = m1 + 8;
        int n1 = snode[m1], n2 = snode[m2];
#pragma unroll
        for (int nt = 0; nt < N_TILES; nt++) {
            int col = blockIdx.y * BN + warp_n0 + nt * 8 + gcol;
            if (n1 >= 0)
                *(__half2*)(S + (size_t)n1 * NOUT + col) =
                    __floats2half2_rn(acc[mt][nt][0], acc[mt][nt][1]);
            if (n2 >= 0)
                *(__half2*)(S + (size_t)n2 * NOUT + col) =
                    __floats2half2_rn(acc[mt][nt][2], acc[mt][nt][3]);
        }
    }
}

// ---------------- sparse aggregation (gather by dst, CSR, fp16 support) ----------------
template <int WID, typename TOUT>
__global__ void __launch_bounds__(256)
k_spmm(const __half* __restrict__ S, TOUT* __restrict__ O,
       const float* __restrict__ bias, int N, int relu) {
    int wid = (blockIdx.x * blockDim.x + threadIdx.x) >> 5;
    int lane = threadIdx.x & 31;
    if (wid >= N) return;
    int s = g_row_ptr[wid], e = g_row_ptr[wid + 1];

    if (WID == 256) {
        float acc[8];
#pragma unroll
        for (int q = 0; q < 8; q++) acc[q] = 0.0f;

        int i = s;
        for (; i + 4 <= e; i += 4) {
            int s0 = g_csr_src[i], s1 = g_csr_src[i + 1];
            int s2 = g_csr_src[i + 2], s3 = g_csr_src[i + 3];
            float w0 = g_csr_w[i], w1 = g_csr_w[i + 1];
            float w2 = g_csr_w[i + 2], w3 = g_csr_w[i + 3];
            uint4 q0 = *(const uint4*)(S + (size_t)s0 * 256 + lane * 8);
            uint4 q1 = *(const uint4*)(S + (size_t)s1 * 256 + lane * 8);
            uint4 q2 = *(const uint4*)(S + (size_t)s2 * 256 + lane * 8);
            uint4 q3 = *(const uint4*)(S + (size_t)s3 * 256 + lane * 8);
#pragma unroll
            for (int h = 0; h < 4; h++) {
                float2 f0 = __half22float2(((const __half2*)&q0)[h]);
                float2 f1 = __half22float2(((const __half2*)&q1)[h]);
                float2 f2 = __half22float2(((const __half2*)&q2)[h]);
                float2 f3 = __half22float2(((const __half2*)&q3)[h]);
                acc[h * 2 + 0] = fmaf(w0, f0.x, acc[h * 2 + 0]);
                acc[h * 2 + 1] = fmaf(w0, f0.y, acc[h * 2 + 1]);
                acc[h * 2 + 0] = fmaf(w1, f1.x, acc[h * 2 + 0]);
                acc[h * 2 + 1] = fmaf(w1, f1.y, acc[h * 2 + 1]);
                acc[h * 2 + 0] = fmaf(w2, f2.x, acc[h * 2 + 0]);
                acc[h * 2 + 1] = fmaf(w2, f2.y, acc[h * 2 + 1]);
                acc[h * 2 + 0] = fmaf(w3, f3.x, acc[h * 2 + 0]);
                acc[h * 2 + 1] = fmaf(w3, f3.y, acc[h * 2 + 1]);
            }
        }
        for (; i < e; i++) {
            int s0 = g_csr_src[i];
            float w0 = g_csr_w[i];
            uint4 q0 = *(const uint4*)(S + (size_t)s0 * 256 + lane * 8);
#pragma unroll
            for (int h = 0; h < 4; h++) {
                float2 f0 = __half22float2(((const __half2*)&q0)[h]);
                acc[h * 2 + 0] = fmaf(w0, f0.x, acc[h * 2 + 0]);
                acc[h * 2 + 1] = fmaf(w0, f0.y, acc[h * 2 + 1]);
            }
        }
        float4 b0 = *(const float4*)(bias + lane * 8);
        float4 b1 = *(const float4*)(bias + lane * 8 + 4);
        acc[0] += b0.x; acc[1] += b0.y; acc[2] += b0.z; acc[3] += b0.w;
        acc[4] += b1.x; acc[5] += b1.y; acc[6] += b1.z; acc[7] += b1.w;
        if (relu) {
#pragma unroll
            for (int q = 0; q < 8; q++) acc[q] = fmaxf(acc[q], 0.0f);
        }
        if (sizeof(TOUT) == 4) {
            float* o = (float*)O + (size_t)wid * 256 + lane * 8;
            float4 v0 = {acc[0], acc[1], acc[2], acc[3]};
            float4 v1 = {acc[4], acc[5], acc[6], acc[7]};
            *(float4*)o = v0;
            *(float4*)(o + 4) = v1;
        } else {
            uint4 v;
            v.x = h2u(__floats2half2_rn(acc[0], acc[1]));
            v.y = h2u(__floats2half2_rn(acc[2], acc[3]));
            v.z = h2u(__floats2half2_rn(acc[4], acc[5]));
            v.w = h2u(__floats2half2_rn(acc[6], acc[7]));
            *(uint4*)((__half*)O + (size_t)wid * 256 + lane * 8) = v;
        }
    } else {  // WID == 64
        float2 acc = {0, 0};
        int i = s;
        for (; i + 4 <= e; i += 4) {
            int s0 = g_csr_src[i], s1 = g_csr_src[i + 1];
            int s2 = g_csr_src[i + 2], s3 = g_csr_src[i + 3];
            float w0 = g_csr_w[i], w1 = g_csr_w[i + 1];
            float w2 = g_csr_w[i + 2], w3 = g_csr_w[i + 3];
            __half2 h0 = *(const __half2*)(S + (size_t)s0 * 64 + lane * 2);
            __half2 h1 = *(const __half2*)(S + (size_t)s1 * 64 + lane * 2);
            __half2 h2 = *(const __half2*)(S + (size_t)s2 * 64 + lane * 2);
            __half2 h3 = *(const __half2*)(S + (size_t)s3 * 64 + lane * 2);
            float2 f0 = __half22float2(h0), f1 = __half22float2(h1);
            float2 f2 = __half22float2(h2), f3 = __half22float2(h3);
            acc.x = fmaf(w0, f0.x, acc.x); acc.y = fmaf(w0, f0.y, acc.y);
            acc.x = fmaf(w1, f1.x, acc.x); acc.y = fmaf(w1, f1.y, acc.y);
            acc.x = fmaf(w2, f2.x, acc.x); acc.y = fmaf(w2, f2.y, acc.y);
            acc.x = fmaf(w3, f3.x, acc.x); acc.y = fmaf(w3, f3.y, acc.y);
        }
        for (; i < e; i++) {
            int s0 = g_csr_src[i];
            float w0 = g_csr_w[i];
            float2 f0 = __half22float2(*(const __half2*)(S + (size_t)s0 * 64 + lane * 2));
            acc.x = fmaf(w0, f0.x, acc.x); acc.y = fmaf(w0, f0.y, acc.y);
        }
        float2 b = *(const float2*)(bias + lane * 2);
        acc.x += b.x; acc.y += b.y;
        if (relu) { acc.x = fmaxf(acc.x, 0.f); acc.y = fmaxf(acc.y, 0.f); }
        if (sizeof(TOUT) == 4) {
            *(float2*)((float*)O + (size_t)wid * 64 + lane * 2) = acc;
        } else {
            *(__half2*)((__half*)O + (size_t)wid * 64 + lane * 2) = __floats2half2_rn(acc.x, acc.y);
        }
    }
}

// ---------------- launch ----------------
extern "C" void kernel_launch(void* const* d_in, const int* in_sizes, int n_in,
                              void* d_out, int out_size) {
    const float* x    = (const float*)d_in[0];
    const int*   esrc = (const int*)d_in[1];
    const int*   edst = (const int*)d_in[2];
    const float* ew   = (const float*)d_in[3];
    const int*   lab  = (const int*)d_in[4];
    const float* W1   = (const float*)d_in[5];
    const float* b1   = (const float*)d_in[6];
    const float* W2   = (const float*)d_in[7];
    const float* b2   = (const float*)d_in[8];
    const float* W3   = (const float*)d_in[9];
    const float* b3   = (const float*)d_in[10];
    float* out = (float*)d_out;

    int N = in_sizes[4];
    int E = in_sizes[1];

    void *p_cnt, *p_labcnt, *p_bufH, *p_bufF;
    void *p_w1h, *p_w1l, *p_w2h, *p_w2l, *p_w3h, *p_w3l;
    cudaGetSymbolAddress(&p_cnt, g_cnt);
    cudaGetSymbolAddress(&p_labcnt, g_lab_cnt);
    cudaGetSymbolAddress(&p_bufH, g_bufH);
    cudaGetSymbolAddress(&p_bufF, g_bufF);
    cudaGetSymbolAddress(&p_w1h, g_W1hi); cudaGetSymbolAddress(&p_w1l, g_W1lo);
    cudaGetSymbolAddress(&p_w2h, g_W2hi); cudaGetSymbolAddress(&p_w2l, g_W2lo);
    cudaGetSymbolAddress(&p_w3h, g_W3hi); cudaGetSymbolAddress(&p_w3l, g_W3lo);
    __half* bufH = (__half*)p_bufH;
    __half* bufF = (__half*)p_bufF;

    // dynamic smem sizes
    const int ASZ = 128 * 40, BSZ128 = 32 * 136, BSZ64 = 32 * 72;
    const int SMEM_W = (4 * ASZ + 4 * BSZ128) * 2;  // bytes
    const int SMEM_N = (4 * ASZ + 4 * BSZ64) * 2;
    cudaFuncSetAttribute(k_gemm_mma<128, float>,  cudaFuncAttributeMaxDynamicSharedMemorySize, SMEM_W);
    cudaFuncSetAttribute(k_gemm_mma<128, __half>, cudaFuncAttributeMaxDynamicSharedMemorySize, SMEM_W);
    cudaFuncSetAttribute(k_gemm_mma<64, __half>,  cudaFuncAttributeMaxDynamicSharedMemorySize, SMEM_N);

    static cudaStream_t s2 = nullptr;
    static cudaEvent_t evFork = nullptr, evJoin = nullptr;
    if (s2 == nullptr) {
        cudaStreamCreateWithFlags(&s2, cudaStreamNonBlocking);
        cudaEventCreateWithFlags(&evFork, cudaEventDisableTiming);
        cudaEventCreateWithFlags(&evJoin, cudaEventDisableTiming);
    }

    const int tpb = 256;

    // ---- fork: CSR build + W2/W3 split on s2; label grouping + W1 split + GEMM1 on main
    cudaEventRecord(evFork, 0);
    cudaStreamWaitEvent(s2, evFork, 0);

    cudaMemsetAsync(p_cnt, 0, (size_t)N * sizeof(int), s2);
    k_hist_edges<<<1024, tpb, 0, s2>>>(edst, E);
    k_scan_rows<<<1, 1024, 0, s2>>>(N);
    k_scatter_edges<<<1024, tpb, 0, s2>>>(esrc, edst, ew, E);
    k_wsplit<<<256, tpb, 0, s2>>>(W2, (__nv_bfloat16*)p_w2h, (__nv_bfloat16*)p_w2l, 4 * 256 * 256);
    k_wsplit<<<64, tpb, 0, s2>>>(W3, (__nv_bfloat16*)p_w3h, (__nv_bfloat16*)p_w3l, 4 * 256 * 64);
    cudaEventRecord(evJoin, s2);

    cudaMemsetAsync(p_labcnt, 0, 4 * sizeof(int), 0);
    k_hist_labels<<<128, tpb>>>(lab, N);
    k_scan_labels<<<1, 32>>>();
    k_scatter_perm<<<(N + tpb - 1) / tpb, tpb>>>(lab, N);
    k_wsplit<<<256, tpb>>>(W1, (__nv_bfloat16*)p_w1h, (__nv_bfloat16*)p_w1l, 4 * 256 * 256);

    int rt = (N + 127) / 128 + 4;
    int spmm_blocks = (N * 32 + tpb - 1) / tpb;

    // layer 1 dense (independent of CSR)
    k_gemm_mma<128, float><<<dim3(rt, 2), 256, SMEM_W>>>(
        x, (const __nv_bfloat16*)p_w1h, (const __nv_bfloat16*)p_w1l, bufH, 256);

    cudaStreamWaitEvent(0, evJoin, 0);

    k_spmm<256, __half><<<spmm_blocks, tpb>>>(bufH, bufF, b1, N, 1);
    // layer 2
    k_gemm_mma<128, __half><<<dim3(rt, 2), 256, SMEM_W>>>(
        bufF, (const __nv_bfloat16*)p_w2h, (const __nv_bfloat16*)p_w2l, bufH, 256);
    k_spmm<256, __half><<<spmm_blocks, tpb>>>(bufH, bufF, b2, N, 1);
    // layer 3
    k_gemm_mma<64, __half><<<dim3(rt, 1), 256, SMEM_N>>>(
        bufF, (const __nv_bfloat16*)p_w3h, (const __nv_bfloat16*)p_w3l, bufH, 64);
    k_spmm<64, float><<<spmm_blocks, tpb>>>(bufH, out, b3, N, 0);
}

// round 7
// speedup vs baseline: 2.2477x; 1.0036x over previous
#include <cuda_runtime.h>
#include <cuda_fp16.h>
#include <cuda_bf16.h>
#include <cstdint>

#define NMAX 50048
#define EMAX 1600000

// ---------------- scratch (static device globals; no allocation) ----------------
__device__ __half g_bufH1[(size_t)NMAX * 256];  // fp16 support (layers 1,3)
__device__ __half g_bufH2[(size_t)NMAX * 256];  // fp16 support (layer 2)
__device__ __half g_bufF[(size_t)NMAX * 256];   // fp16 features (SpMM out / GEMM in)
__device__ int    g_csr_src[EMAX];
__device__ float  g_csr_w[EMAX];
__device__ int    g_cnt[NMAX];
__device__ int    g_row_ptr[NMAX + 1];
__device__ int    g_perm[8 * NMAX];             // 8 groups: (half, label), each at grp*NMAX
__device__ int    g_lab_cur[8];                 // cursors -> group counts
// pre-split bf16 weights, same [4][K][NOUT] layout as source
__device__ __nv_bfloat16 g_W1hi[4 * 256 * 256];
__device__ __nv_bfloat16 g_W1lo[4 * 256 * 256];
__device__ __nv_bfloat16 g_W2hi[4 * 256 * 256];
__device__ __nv_bfloat16 g_W2lo[4 * 256 * 256];
__device__ __nv_bfloat16 g_W3hi[4 * 256 * 64];
__device__ __nv_bfloat16 g_W3lo[4 * 256 * 64];

// ---------------- mma / ldmatrix helpers ----------------
__device__ __forceinline__ void ldsm_x4(uint32_t* r, uint32_t addr) {
    asm volatile("ldmatrix.sync.aligned.m8n8.x4.shared.b16 {%0,%1,%2,%3}, [%4];"
                 : "=r"(r[0]), "=r"(r[1]), "=r"(r[2]), "=r"(r[3]) : "r"(addr));
}
__device__ __forceinline__ void ldsm_x2t(uint32_t* r, uint32_t addr) {
    asm volatile("ldmatrix.sync.aligned.m8n8.x2.trans.shared.b16 {%0,%1}, [%2];"
                 : "=r"(r[0]), "=r"(r[1]) : "r"(addr));
}
__device__ __forceinline__ void mma_bf16(float* c, const uint32_t* a, const uint32_t* b) {
    asm volatile(
        "mma.sync.aligned.m16n8k16.row.col.f32.bf16.bf16.f32 "
        "{%0,%1,%2,%3}, {%4,%5,%6,%7}, {%8,%9}, {%0,%1,%2,%3};"
        : "+f"(c[0]), "+f"(c[1]), "+f"(c[2]), "+f"(c[3])
        : "r"(a[0]), "r"(a[1]), "r"(a[2]), "r"(a[3]), "r"(b[0]), "r"(b[1]));
}
__device__ __forceinline__ uint32_t pack_bf2(float a, float b) {
    __nv_bfloat162 t = __floats2bfloat162_rn(a, b);
    return *reinterpret_cast<uint32_t*>(&t);
}
__device__ __forceinline__ uint32_t h2u(__half2 h) { return *reinterpret_cast<uint32_t*>(&h); }

// ---------------- CSR build ----------------
__global__ void k_hist_edges(const int* __restrict__ dst, int E) {
    int i = blockIdx.x * blockDim.x + threadIdx.x;
    int stride = gridDim.x * blockDim.x;
    for (; i < E; i += stride) atomicAdd(&g_cnt[dst[i]], 1);
}

__global__ void k_scan_rows(int N) {
    int tid = threadIdx.x;
    int chunk = (N + 1023) / 1024;
    int b = tid * chunk;
    int e = b + chunk; if (e > N) e = N;
    int s = 0;
    for (int i = b; i < e; i++) s += g_cnt[i];

    __shared__ int sm[1024];
    sm[tid] = s;
    __syncthreads();
    for (int d = 1; d < 1024; d <<= 1) {
        int v = (tid >= d) ? sm[tid - d] : 0;
        __syncthreads();
        sm[tid] += v;
        __syncthreads();
    }
    int run = sm[tid] - s;
    for (int i = b; i < e; i++) {
        int c = g_cnt[i];
        g_row_ptr[i] = run;
        g_cnt[i] = run;
        run += c;
    }
    if (tid == 1023) g_row_ptr[N] = sm[1023];
}

__global__ void k_scatter_edges(const int* __restrict__ src, const int* __restrict__ dst,
                                const float* __restrict__ w, int E) {
    int i = blockIdx.x * blockDim.x + threadIdx.x;
    int stride = gridDim.x * blockDim.x;
    for (; i < E; i += stride) {
        int p = atomicAdd(&g_cnt[dst[i]], 1);
        g_csr_src[p] = src[i];
        g_csr_w[p] = w[i];
    }
}

// ---------------- grouping: 8 cursor-based bins (half, label) ----------------
__global__ void k_scatter_perm8(const int* __restrict__ lab, int N, int nh) {
    __shared__ int c[8], base[8];
    if (threadIdx.x < 8) c[threadIdx.x] = 0;
    __syncthreads();
    int i = blockIdx.x * blockDim.x + threadIdx.x;
    int grp = 0, local = 0;
    bool valid = (i < N);
    if (valid) {
        grp = lab[i] + ((i >= nh) ? 4 : 0);
        local = atomicAdd(&c[grp], 1);
    }
    __syncthreads();
    if (threadIdx.x < 8)
        base[threadIdx.x] = c[threadIdx.x] ? atomicAdd(&g_lab_cur[threadIdx.x], c[threadIdx.x]) : 0;
    __syncthreads();
    if (valid) g_perm[grp * NMAX + base[grp] + local] = i;
}

// ---------------- weight split: fp32 -> bf16 hi/lo ----------------
__global__ void k_wsplit(const float* __restrict__ W, __nv_bfloat16* __restrict__ Whi,
                         __nv_bfloat16* __restrict__ Wlo, int n) {
    int i = blockIdx.x * blockDim.x + threadIdx.x;
    int stride = gridDim.x * blockDim.x;
    for (; i < n; i += stride) {
        float v = W[i];
        __nv_bfloat16 h = __float2bfloat16(v);
        Whi[i] = h;
        Wlo[i] = __float2bfloat16(v - __bfloat162float(h));
    }
}

// ---------------- tensor-core grouped dense: H = fp16( X @ W[label] ) ----------------
// Covers groups [gbase, gbase+ng). label = grp & 3.
template <int BN, typename TIN>
__global__ void __launch_bounds__(256, 1)
k_gemm_mma(const TIN* __restrict__ X,
           const __nv_bfloat16* __restrict__ Whi,
           const __nv_bfloat16* __restrict__ Wlo,
           __half* __restrict__ S, int NOUT, int gbase, int ng) {
    constexpr int BM = 128, BK = 32, K = 256, CHUNKS = K / BK;
    constexpr int WR_N = (BN == 128) ? 4 : 2;
    constexpr int WM = (BN == 128) ? 64 : 32;
    constexpr int WN = 32;
    constexpr int M_TILES = WM / 16;
    constexpr int N_TILES = WN / 8;
    constexpr int AS = 40;
    constexpr int BS = BN + 8;
    constexpr int ASZ = BM * AS;
    constexpr int BSZ = BK * BS;
    constexpr bool IN32 = (sizeof(TIN) == 4);

    extern __shared__ __align__(16) __nv_bfloat16 dyn[];
    __shared__ int snode[BM];

    int tid = threadIdx.x;
    int w = tid >> 5, lane = tid & 31;
    int wm = w / WR_N, wn = w % WR_N;
    int warp_m0 = wm * WM, warp_n0 = wn * WN;

    // --- group / tile mapping (loop over ng groups) ---
    int bxr = blockIdx.x;
    int g = -1, cnt = 0, tile = 0;
#pragma unroll 1
    for (int gi = 0; gi < ng; gi++) {
        int cg = g_lab_cur[gbase + gi];
        int t = (cg + BM - 1) >> 7;
        if (bxr < t) { g = gbase + gi; cnt = cg; tile = bxr; break; }
        bxr -= t;
    }
    if (g < 0) return;
    int off = g * NMAX;
    int labl = g & 3;

    if (tid < BM) {
        int idx = tile * BM + tid;
        snode[tid] = (idx < cnt) ? g_perm[off + idx] : -1;
    }
    __syncthreads();

    const __nv_bfloat16* WhiG = Whi + (size_t)labl * K * NOUT + blockIdx.y * BN;
    const __nv_bfloat16* WloG = Wlo + (size_t)labl * K * NOUT + blockIdx.y * BN;

    int arow = tid >> 1, ahalf = tid & 1;
    int anode = snode[arow]; if (anode < 0) anode = 0;
    const TIN* aptr = X + (size_t)anode * K + ahalf * 16;

    int brow = tid >> 3, bcolg = tid & 7;
    constexpr int BPT = BN / 8;

    uint32_t dyn_u = (uint32_t)__cvta_generic_to_shared(dyn);
    int a_m = lane & 15, a_koff = (lane >> 4) * 8;
    int b_k = lane & 15;

    float acc[M_TILES][N_TILES][4];
#pragma unroll
    for (int i = 0; i < M_TILES; i++)
#pragma unroll
        for (int j = 0; j < N_TILES; j++)
#pragma unroll
            for (int q = 0; q < 4; q++) acc[i][j][q] = 0.0f;

    float4 av32[4];
    uint4 av16[2];
    uint4 bh0, bh1, bl0, bl1;

    auto loadRegs = [&](int kc) {
        if (IN32) {
            const float* ap = (const float*)aptr + kc;
            av32[0] = *(const float4*)(ap);
            av32[1] = *(const float4*)(ap + 4);
            av32[2] = *(const float4*)(ap + 8);
            av32[3] = *(const float4*)(ap + 12);
        } else {
            const __half* ap = (const __half*)aptr + kc;
            av16[0] = *(const uint4*)(ap);
            av16[1] = *(const uint4*)(ap + 8);
        }
        const __nv_bfloat16* ph = WhiG + (size_t)(kc + brow) * NOUT + bcolg * BPT;
        const __nv_bfloat16* pl = WloG + (size_t)(kc + brow) * NOUT + bcolg * BPT;
        bh0 = *(const uint4*)ph;
        bl0 = *(const uint4*)pl;
        if (BPT == 16) {
            bh1 = *(const uint4*)(ph + 8);
            bl1 = *(const uint4*)(pl + 8);
        }
    };

    auto storeSmem = [&](int buf) {
        float f[16];
        if (IN32) {
            f[0] = av32[0].x; f[1] = av32[0].y; f[2] = av32[0].z; f[3] = av32[0].w;
            f[4] = av32[1].x; f[5] = av32[1].y; f[6] = av32[1].z; f[7] = av32[1].w;
            f[8] = av32[2].x; f[9] = av32[2].y; f[10] = av32[2].z; f[11] = av32[2].w;
            f[12] = av32[3].x; f[13] = av32[3].y; f[14] = av32[3].z; f[15] = av32[3].w;
        } else {
            const __half2* hp = (const __half2*)&av16[0];
#pragma unroll
            for (int q = 0; q < 4; q++) {
                float2 t = __half22float2(hp[q]);
                f[q * 2] = t.x; f[q * 2 + 1] = t.y;
            }
            hp = (const __half2*)&av16[1];
#pragma unroll
            for (int q = 0; q < 4; q++) {
                float2 t = __half22float2(hp[q]);
                f[8 + q * 2] = t.x; f[8 + q * 2 + 1] = t.y;
            }
        }
        uint32_t hp_[8], lp_[8];
#pragma unroll
        for (int q = 0; q < 8; q++) {
            float x0 = f[q * 2], x1 = f[q * 2 + 1];
            __nv_bfloat16 h0 = __float2bfloat16(x0);
            __nv_bfloat16 h1 = __float2bfloat16(x1);
            hp_[q] = pack_bf2(x0, x1);
            lp_[q] = pack_bf2(x0 - __bfloat162float(h0), x1 - __bfloat162float(h1));
        }
        __nv_bfloat16* dh = dyn + buf * (2 * ASZ) + arow * AS + ahalf * 16;
        __nv_bfloat16* dl = dh + ASZ;
        ((uint4*)dh)[0] = make_uint4(hp_[0], hp_[1], hp_[2], hp_[3]);
        ((uint4*)dh)[1] = make_uint4(hp_[4], hp_[5], hp_[6], hp_[7]);
        ((uint4*)dl)[0] = make_uint4(lp_[0], lp_[1], lp_[2], lp_[3]);
        ((uint4*)dl)[1] = make_uint4(lp_[4], lp_[5], lp_[6], lp_[7]);
        __nv_bfloat16* bh = dyn + 4 * ASZ + buf * (2 * BSZ) + brow * BS + bcolg * BPT;
        __nv_bfloat16* bl = bh + BSZ;
        ((uint4*)bh)[0] = bh0;
        ((uint4*)bl)[0] = bl0;
        if (BPT == 16) {
            ((uint4*)bh)[1] = bh1;
            ((uint4*)bl)[1] = bl1;
        }
    };

    loadRegs(0);
    storeSmem(0);
    __syncthreads();

    for (int kc = 0; kc < CHUNKS; kc++) {
        int cur = kc & 1;
        if (kc + 1 < CHUNKS) loadRegs((kc + 1) * BK);

        uint32_t aBase = dyn_u + (uint32_t)(cur * 2 * ASZ) * 2;
        uint32_t bBase = dyn_u + (uint32_t)(4 * ASZ + cur * 2 * BSZ) * 2;
#pragma unroll
        for (int ks = 0; ks < 2; ks++) {
            uint32_t afh[M_TILES][4], afl[M_TILES][4];
            uint32_t bfh[N_TILES][2], bfl[N_TILES][2];
#pragma unroll
            for (int mt = 0; mt < M_TILES; mt++) {
                uint32_t ra = aBase + (uint32_t)((warp_m0 + mt * 16 + a_m) * AS + ks * 16 + a_koff) * 2;
                ldsm_x4(afh[mt], ra);
                ldsm_x4(afl[mt], ra + ASZ * 2);
            }
#pragma unroll
            for (int nt = 0; nt < N_TILES; nt++) {
                uint32_t rb = bBase + (uint32_t)((ks * 16 + b_k) * BS + warp_n0 + nt * 8) * 2;
                ldsm_x2t(bfh[nt], rb);
                ldsm_x2t(bfl[nt], rb + BSZ * 2);
            }
#pragma unroll
            for (int mt = 0; mt < M_TILES; mt++)
#pragma unroll
                for (int nt = 0; nt < N_TILES; nt++) {
                    mma_bf16(acc[mt][nt], afh[mt], bfh[nt]);
                    mma_bf16(acc[mt][nt], afh[mt], bfl[nt]);
                    mma_bf16(acc[mt][nt], afl[mt], bfh[nt]);
                }
        }

        if (kc + 1 < CHUNKS) storeSmem(cur ^ 1);
        __syncthreads();
    }

    int grow = lane >> 2, gcol = (lane & 3) * 2;
#pragma unroll
    for (int mt = 0; mt < M_TILES; mt++) {
        int m1 = warp_m0 + mt * 16 + grow;
        int m2 = m1 + 8;
        int n1 = snode[m1], n2 = snode[m2];
#pragma unroll
        for (int nt = 0; nt < N_TILES; nt++) {
            int col = blockIdx.y * BN + warp_n0 + nt * 8 + gcol;
            if (n1 >= 0)
                *(__half2*)(S + (size_t)n1 * NOUT + col) =
                    __floats2half2_rn(acc[mt][nt][0], acc[mt][nt][1]);
            if (n2 >= 0)
                *(__half2*)(S + (size_t)n2 * NOUT + col) =
                    __floats2half2_rn(acc[mt][nt][2], acc[mt][nt][3]);
        }
    }
}

// ---------------- sparse aggregation: dst range [n0, n1) ----------------
template <int WID, typename TOUT>
__global__ void __launch_bounds__(256)
k_spmm(const __half* __restrict__ S, TOUT* __restrict__ O,
       const float* __restrict__ bias, int n0, int n1, int relu) {
    int wid = ((blockIdx.x * blockDim.x + threadIdx.x) >> 5) + n0;
    int lane = threadIdx.x & 31;
    if (wid >= n1) return;
    int s = g_row_ptr[wid], e = g_row_ptr[wid + 1];

    if (WID == 256) {
        float acc[8];
#pragma unroll
        for (int q = 0; q < 8; q++) acc[q] = 0.0f;

        int i = s;
        for (; i + 4 <= e; i += 4) {
            int s0 = g_csr_src[i], s1 = g_csr_src[i + 1];
            int s2 = g_csr_src[i + 2], s3 = g_csr_src[i + 3];
            float w0 = g_csr_w[i], w1 = g_csr_w[i + 1];
            float w2 = g_csr_w[i + 2], w3 = g_csr_w[i + 3];
            uint4 q0 = *(const uint4*)(S + (size_t)s0 * 256 + lane * 8);
            uint4 q1 = *(const uint4*)(S + (size_t)s1 * 256 + lane * 8);
            uint4 q2 = *(const uint4*)(S + (size_t)s2 * 256 + lane * 8);
            uint4 q3 = *(const uint4*)(S + (size_t)s3 * 256 + lane * 8);
#pragma unroll
            for (int h = 0; h < 4; h++) {
                float2 f0 = __half22float2(((const __half2*)&q0)[h]);
                float2 f1 = __half22float2(((const __half2*)&q1)[h]);
                float2 f2 = __half22float2(((const __half2*)&q2)[h]);
                float2 f3 = __half22float2(((const __half2*)&q3)[h]);
                acc[h * 2 + 0] = fmaf(w0, f0.x, acc[h * 2 + 0]);
                acc[h * 2 + 1] = fmaf(w0, f0.y, acc[h * 2 + 1]);
                acc[h * 2 + 0] = fmaf(w1, f1.x, acc[h * 2 + 0]);
                acc[h * 2 + 1] = fmaf(w1, f1.y, acc[h * 2 + 1]);
                acc[h * 2 + 0] = fmaf(w2, f2.x, acc[h * 2 + 0]);
                acc[h * 2 + 1] = fmaf(w2, f2.y, acc[h * 2 + 1]);
                acc[h * 2 + 0] = fmaf(w3, f3.x, acc[h * 2 + 0]);
                acc[h * 2 + 1] = fmaf(w3, f3.y, acc[h * 2 + 1]);
            }
        }
        for (; i < e; i++) {
            int s0 = g_csr_src[i];
            float w0 = g_csr_w[i];
            uint4 q0 = *(const uint4*)(S + (size_t)s0 * 256 + lane * 8);
#pragma unroll
            for (int h = 0; h < 4; h++) {
                float2 f0 = __half22float2(((const __half2*)&q0)[h]);
                acc[h * 2 + 0] = fmaf(w0, f0.x, acc[h * 2 + 0]);
                acc[h * 2 + 1] = fmaf(w0, f0.y, acc[h * 2 + 1]);
            }
        }
        float4 b0 = *(const float4*)(bias + lane * 8);
        float4 b1 = *(const float4*)(bias + lane * 8 + 4);
        acc[0] += b0.x; acc[1] += b0.y; acc[2] += b0.z; acc[3] += b0.w;
        acc[4] += b1.x; acc[5] += b1.y; acc[6] += b1.z; acc[7] += b1.w;
        if (relu) {
#pragma unroll
            for (int q = 0; q < 8; q++) acc[q] = fmaxf(acc[q], 0.0f);
        }
        if (sizeof(TOUT) == 4) {
            float* o = (float*)O + (size_t)wid * 256 + lane * 8;
            float4 v0 = {acc[0], acc[1], acc[2], acc[3]};
            float4 v1 = {acc[4], acc[5], acc[6], acc[7]};
            *(float4*)o = v0;
            *(float4*)(o + 4) = v1;
        } else {
            uint4 v;
            v.x = h2u(__floats2half2_rn(acc[0], acc[1]));
            v.y = h2u(__floats2half2_rn(acc[2], acc[3]));
            v.z = h2u(__floats2half2_rn(acc[4], acc[5]));
            v.w = h2u(__floats2half2_rn(acc[6], acc[7]));
            *(uint4*)((__half*)O + (size_t)wid * 256 + lane * 8) = v;
        }
    } else {  // WID == 64
        float2 acc = {0, 0};
        int i = s;
        for (; i + 4 <= e; i += 4) {
            int s0 = g_csr_src[i], s1 = g_csr_src[i + 1];
            int s2 = g_csr_src[i + 2], s3 = g_csr_src[i + 3];
            float w0 = g_csr_w[i], w1 = g_csr_w[i + 1];
            float w2 = g_csr_w[i + 2], w3 = g_csr_w[i + 3];
            __half2 h0 = *(const __half2*)(S + (size_t)s0 * 64 + lane * 2);
            __half2 h1 = *(const __half2*)(S + (size_t)s1 * 64 + lane * 2);
            __half2 h2 = *(const __half2*)(S + (size_t)s2 * 64 + lane * 2);
            __half2 h3 = *(const __half2*)(S + (size_t)s3 * 64 + lane * 2);
            float2 f0 = __half22float2(h0), f1 = __half22float2(h1);
            float2 f2 = __half22float2(h2), f3 = __half22float2(h3);
            acc.x = fmaf(w0, f0.x, acc.x); acc.y = fmaf(w0, f0.y, acc.y);
            acc.x = fmaf(w1, f1.x, acc.x); acc.y = fmaf(w1, f1.y, acc.y);
            acc.x = fmaf(w2, f2.x, acc.x); acc.y = fmaf(w2, f2.y, acc.y);
            acc.x = fmaf(w3, f3.x, acc.x); acc.y = fmaf(w3, f3.y, acc.y);
        }
        for (; i < e; i++) {
            int s0 = g_csr_src[i];
            float w0 = g_csr_w[i];
            float2 f0 = __half22float2(*(const __half2*)(S + (size_t)s0 * 64 + lane * 2));
            acc.x = fmaf(w0, f0.x, acc.x); acc.y = fmaf(w0, f0.y, acc.y);
        }
        float2 b = *(const float2*)(bias + lane * 2);
        acc.x += b.x; acc.y += b.y;
        if (relu) { acc.x = fmaxf(acc.x, 0.f); acc.y = fmaxf(acc.y, 0.f); }
        if (sizeof(TOUT) == 4) {
            *(float2*)((float*)O + (size_t)wid * 64 + lane * 2) = acc;
        } else {
            *(__half2*)((__half*)O + (size_t)wid * 64 + lane * 2) = __floats2half2_rn(acc.x, acc.y);
        }
    }
}

// ---------------- launch ----------------
extern "C" void kernel_launch(void* const* d_in, const int* in_sizes, int n_in,
                              void* d_out, int out_size) {
    const float* x    = (const float*)d_in[0];
    const int*   esrc = (const int*)d_in[1];
    const int*   edst = (const int*)d_in[2];
    const float* ew   = (const float*)d_in[3];
    const int*   lab  = (const int*)d_in[4];
    const float* W1   = (const float*)d_in[5];
    const float* b1   = (const float*)d_in[6];
    const float* W2   = (const float*)d_in[7];
    const float* b2   = (const float*)d_in[8];
    const float* W3   = (const float*)d_in[9];
    const float* b3   = (const float*)d_in[10];
    float* out = (float*)d_out;

    int N = in_sizes[4];
    int E = in_sizes[1];
    int nh = N / 2;

    void *p_cnt, *p_cur, *p_H1, *p_H2, *p_F;
    void *p_w1h, *p_w1l, *p_w2h, *p_w2l, *p_w3h, *p_w3l;
    cudaGetSymbolAddress(&p_cnt, g_cnt);
    cudaGetSymbolAddress(&p_cur, g_lab_cur);
    cudaGetSymbolAddress(&p_H1, g_bufH1);
    cudaGetSymbolAddress(&p_H2, g_bufH2);
    cudaGetSymbolAddress(&p_F, g_bufF);
    cudaGetSymbolAddress(&p_w1h, g_W1hi); cudaGetSymbolAddress(&p_w1l, g_W1lo);
    cudaGetSymbolAddress(&p_w2h, g_W2hi); cudaGetSymbolAddress(&p_w2l, g_W2lo);
    cudaGetSymbolAddress(&p_w3h, g_W3hi); cudaGetSymbolAddress(&p_w3l, g_W3lo);
    __half* H1 = (__half*)p_H1;
    __half* H2 = (__half*)p_H2;
    __half* F  = (__half*)p_F;
    const __nv_bfloat16 *W1h = (const __nv_bfloat16*)p_w1h, *W1l = (const __nv_bfloat16*)p_w1l;
    const __nv_bfloat16 *W2h = (const __nv_bfloat16*)p_w2h, *W2l = (const __nv_bfloat16*)p_w2l;
    const __nv_bfloat16 *W3h = (const __nv_bfloat16*)p_w3h, *W3l = (const __nv_bfloat16*)p_w3l;

    // dynamic smem sizes
    const int ASZ = 128 * 40, BSZ128 = 32 * 136, BSZ64 = 32 * 72;
    const int SMEM_W = (4 * ASZ + 4 * BSZ128) * 2;
    const int SMEM_N = (4 * ASZ + 4 * BSZ64) * 2;
    cudaFuncSetAttribute(k_gemm_mma<128, float>,  cudaFuncAttributeMaxDynamicSharedMemorySize, SMEM_W);
    cudaFuncSetAttribute(k_gemm_mma<128, __half>, cudaFuncAttributeMaxDynamicSharedMemorySize, SMEM_W);
    cudaFuncSetAttribute(k_gemm_mma<64, __half>,  cudaFuncAttributeMaxDynamicSharedMemorySize, SMEM_N);

    static cudaStream_t s2 = nullptr;
    static cudaEvent_t evFork, evJoin, evW, evG1, evS1b, evG2, evS2b, evG3, evS3b;
    if (s2 == nullptr) {
        cudaStreamCreateWithFlags(&s2, cudaStreamNonBlocking);
        cudaEventCreateWithFlags(&evFork, cudaEventDisableTiming);
        cudaEventCreateWithFlags(&evJoin, cudaEventDisableTiming);
        cudaEventCreateWithFlags(&evW, cudaEventDisableTiming);
        cudaEventCreateWithFlags(&evG1, cudaEventDisableTiming);
        cudaEventCreateWithFlags(&evS1b, cudaEventDisableTiming);
        cudaEventCreateWithFlags(&evG2, cudaEventDisableTiming);
        cudaEventCreateWithFlags(&evS2b, cudaEventDisableTiming);
        cudaEventCreateWithFlags(&evG3, cudaEventDisableTiming);
        cudaEventCreateWithFlags(&evS3b, cudaEventDisableTiming);
    }

    const int tpb = 256;
    int rtF = (N + 127) / 128 + 8;       // full (8 groups)
    int rtH = (nh + 255) / 128 + 4;      // half (4 groups), generous
    int spA = ((nh) * 32 + tpb - 1) / tpb;           // dst [0, nh)
    int spB = ((N - nh) * 32 + tpb - 1) / tpb;       // dst [nh, N)

    // ---- fork ----
    cudaEventRecord(evFork, 0);
    cudaStreamWaitEvent(s2, evFork, 0);

    // s2: CSR build, then weight splits
    cudaMemsetAsync(p_cnt, 0, (size_t)N * sizeof(int), s2);
    k_hist_edges<<<1024, tpb, 0, s2>>>(edst, E);
    k_scan_rows<<<1, 1024, 0, s2>>>(N);
    k_scatter_edges<<<1024, tpb, 0, s2>>>(esrc, edst, ew, E);
    cudaEventRecord(evJoin, s2);
    k_wsplit<<<256, tpb, 0, s2>>>(W2, (__nv_bfloat16*)p_w2h, (__nv_bfloat16*)p_w2l, 4 * 256 * 256);
    k_wsplit<<<64, tpb, 0, s2>>>(W3, (__nv_bfloat16*)p_w3h, (__nv_bfloat16*)p_w3l, 4 * 256 * 64);
    cudaEventRecord(evW, s2);

    // main: grouping + W1 split + GEMM1 (full)
    cudaMemsetAsync(p_cur, 0, 8 * sizeof(int), 0);
    k_scatter_perm8<<<(N + tpb - 1) / tpb, tpb>>>(lab, N, nh);
    k_wsplit<<<256, tpb>>>(W1, (__nv_bfloat16*)p_w1h, (__nv_bfloat16*)p_w1l, 4 * 256 * 256);
    k_gemm_mma<128, float><<<dim3(rtF, 2), 256, SMEM_W>>>(x, W1h, W1l, H1, 256, 0, 8);
    cudaEventRecord(evG1, 0);

    // main: SpMM1a needs CSR
    cudaStreamWaitEvent(0, evJoin, 0);
    k_spmm<256, __half><<<spA, tpb>>>(H1, F, b1, 0, nh, 1);

    // s2: SpMM1b (CSR in program order; needs GEMM1)
    cudaStreamWaitEvent(s2, evG1, 0);
    k_spmm<256, __half><<<spB, tpb, 0, s2>>>(H1, F, b1, nh, N, 1);
    cudaEventRecord(evS1b, s2);

    // main: GEMM2a (half0) overlaps SpMM1b
    cudaStreamWaitEvent(0, evW, 0);
    k_gemm_mma<128, __half><<<dim3(rtH, 2), 256, SMEM_W>>>(F, W2h, W2l, H2, 256, 0, 4);
    cudaStreamWaitEvent(0, evS1b, 0);
    k_gemm_mma<128, __half><<<dim3(rtH, 2), 256, SMEM_W>>>(F, W2h, W2l, H2, 256, 4, 4);
    cudaEventRecord(evG2, 0);

    // main: SpMM2a; s2: SpMM2b
    k_spmm<256, __half><<<spA, tpb>>>(H2, F, b2, 0, nh, 1);
    cudaStreamWaitEvent(s2, evG2, 0);
    k_spmm<256, __half><<<spB, tpb, 0, s2>>>(H2, F, b2, nh, N, 1);
    cudaEventRecord(evS2b, s2);

    // main: GEMM3a overlaps SpMM2b
    k_gemm_mma<64, __half><<<dim3(rtH, 1), 256, SMEM_N>>>(F, W3h, W3l, H1, 64, 0, 4);
    cudaStreamWaitEvent(0, evS2b, 0);
    k_gemm_mma<64, __half><<<dim3(rtH, 1), 256, SMEM_N>>>(F, W3h, W3l, H1, 64, 4, 4);
    cudaEventRecord(evG3, 0);

    // SpMM3 split across streams
    k_spmm<64, float><<<spA, tpb>>>(H1, out, b3, 0, nh, 0);
    cudaStreamWaitEvent(s2, evG3, 0);
    k_spmm<64, float><<<spB, tpb, 0, s2>>>(H1, out, b3, nh, N, 0);
    cudaEventRecord(evS3b, s2);
    cudaStreamWaitEvent(0, evS3b, 0);
}

// round 9
// speedup vs baseline: 2.4361x; 1.0838x over previous
#include <cuda_runtime.h>
#include <cuda_fp16.h>
#include <cstdint>

#define NMAX 50048
#define EMAX 1600000

// ---------------- scratch (static device globals; no allocation) ----------------
__device__ __half g_bufH1[(size_t)NMAX * 256];  // fp16 support (layers 1,3)
__device__ __half g_bufH2[(size_t)NMAX * 256];  // fp16 support (layer 2)
__device__ __half g_bufF[(size_t)NMAX * 256];   // fp16 features (SpMM out / GEMM in)
__device__ int    g_csr_src[EMAX];
__device__ float  g_csr_w[EMAX];
__device__ int    g_cnt[NMAX];
__device__ int    g_row_ptr[NMAX + 1];
__device__ int    g_perm[8 * NMAX];             // 8 groups: (half, label), each at grp*NMAX
__device__ int    g_lab_cur[8];                 // cursors -> group counts
// pre-split fp16 weights (hi = fp16(W), lo = fp16(W - hi)), [4][K][NOUT] layout
__device__ __half g_W1hi[4 * 256 * 256];
__device__ __half g_W1lo[4 * 256 * 256];
__device__ __half g_W2hi[4 * 256 * 256];
__device__ __half g_W2lo[4 * 256 * 256];
__device__ __half g_W3hi[4 * 256 * 64];
__device__ __half g_W3lo[4 * 256 * 64];

// ---------------- mma / ldmatrix helpers ----------------
__device__ __forceinline__ void ldsm_x4(uint32_t* r, uint32_t addr) {
    asm volatile("ldmatrix.sync.aligned.m8n8.x4.shared.b16 {%0,%1,%2,%3}, [%4];"
                 : "=r"(r[0]), "=r"(r[1]), "=r"(r[2]), "=r"(r[3]) : "r"(addr));
}
__device__ __forceinline__ void ldsm_x2t(uint32_t* r, uint32_t addr) {
    asm volatile("ldmatrix.sync.aligned.m8n8.x2.trans.shared.b16 {%0,%1}, [%2];"
                 : "=r"(r[0]), "=r"(r[1]) : "r"(addr));
}
__device__ __forceinline__ void mma_f16(float* c, const uint32_t* a, const uint32_t* b) {
    asm volatile(
        "mma.sync.aligned.m16n8k16.row.col.f32.f16.f16.f32 "
        "{%0,%1,%2,%3}, {%4,%5,%6,%7}, {%8,%9}, {%0,%1,%2,%3};"
        : "+f"(c[0]), "+f"(c[1]), "+f"(c[2]), "+f"(c[3])
        : "r"(a[0]), "r"(a[1]), "r"(a[2]), "r"(a[3]), "r"(b[0]), "r"(b[1]));
}
__device__ __forceinline__ uint32_t h2u(__half2 h) { return *reinterpret_cast<uint32_t*>(&h); }

// ---------------- CSR build ----------------
__global__ void k_hist_edges(const int* __restrict__ dst, int E) {
    int i = blockIdx.x * blockDim.x + threadIdx.x;
    int stride = gridDim.x * blockDim.x;
    for (; i < E; i += stride) atomicAdd(&g_cnt[dst[i]], 1);
}

__global__ void k_scan_rows(int N) {
    int tid = threadIdx.x;
    int chunk = (N + 1023) / 1024;
    int b = tid * chunk;
    int e = b + chunk; if (e > N) e = N;
    int s = 0;
    for (int i = b; i < e; i++) s += g_cnt[i];

    __shared__ int sm[1024];
    sm[tid] = s;
    __syncthreads();
    for (int d = 1; d < 1024; d <<= 1) {
        int v = (tid >= d) ? sm[tid - d] : 0;
        __syncthreads();
        sm[tid] += v;
        __syncthreads();
    }
    int run = sm[tid] - s;
    for (int i = b; i < e; i++) {
        int c = g_cnt[i];
        g_row_ptr[i] = run;
        g_cnt[i] = run;
        run += c;
    }
    if (tid == 1023) g_row_ptr[N] = sm[1023];
}

__global__ void k_scatter_edges(const int* __restrict__ src, const int* __restrict__ dst,
                                const float* __restrict__ w, int E) {
    int i = blockIdx.x * blockDim.x + threadIdx.x;
    int stride = gridDim.x * blockDim.x;
    for (; i < E; i += stride) {
        int p = atomicAdd(&g_cnt[dst[i]], 1);
        g_csr_src[p] = src[i];
        g_csr_w[p] = w[i];
    }
}

// ---------------- grouping: 8 cursor-based bins (half, label) ----------------
__global__ void k_scatter_perm8(const int* __restrict__ lab, int N, int nh) {
    __shared__ int c[8], base[8];
    if (threadIdx.x < 8) c[threadIdx.x] = 0;
    __syncthreads();
    int i = blockIdx.x * blockDim.x + threadIdx.x;
    int grp = 0, local = 0;
    bool valid = (i < N);
    if (valid) {
        grp = lab[i] + ((i >= nh) ? 4 : 0);
        local = atomicAdd(&c[grp], 1);
    }
    __syncthreads();
    if (threadIdx.x < 8)
        base[threadIdx.x] = c[threadIdx.x] ? atomicAdd(&g_lab_cur[threadIdx.x], c[threadIdx.x]) : 0;
    __syncthreads();
    if (valid) g_perm[grp * NMAX + base[grp] + local] = i;
}

// ---------------- weight split: fp32 -> fp16 hi/lo ----------------
__global__ void k_wsplit(const float* __restrict__ W, __half* __restrict__ Whi,
                         __half* __restrict__ Wlo, int n) {
    int i = blockIdx.x * blockDim.x + threadIdx.x;
    int stride = gridDim.x * blockDim.x;
    for (; i < n; i += stride) {
        float v = W[i];
        __half h = __float2half_rn(v);
        Whi[i] = h;
        Wlo[i] = __float2half_rn(v - __half2float(h));
    }
}

// ---------------- tensor-core grouped dense: H = fp16( X @ W[label] ) ----------------
// BM=128, BK=32, 256 threads (8 warps). A in fp16 (exact), W fp16-split:
// D = A*Whi + A*Wlo, fp32 accumulators. Double-buffered smem, one sync per chunk.
template <int BN, typename TIN>
__global__ void __launch_bounds__(256, 1)
k_gemm_mma(const TIN* __restrict__ X,
           const __half* __restrict__ Whi,
           const __half* __restrict__ Wlo,
           __half* __restrict__ S, int NOUT, int gbase, int ng) {
    constexpr int BM = 128, BK = 32, K = 256, CHUNKS = K / BK;
    constexpr int WR_N = (BN == 128) ? 4 : 2;
    constexpr int WM = (BN == 128) ? 64 : 32;
    constexpr int WN = 32;
    constexpr int M_TILES = WM / 16;
    constexpr int N_TILES = WN / 8;
    constexpr int AS = 40;                       // A smem stride (halfs)
    constexpr int BS = BN + 8;                   // B smem stride (halfs)
    constexpr int ASZ = BM * AS;                 // one A plane (elems)
    constexpr int BSZ = BK * BS;                 // one B plane (elems)
    constexpr bool IN32 = (sizeof(TIN) == 4);

    extern __shared__ __align__(16) __half dyn[];
    // layout: A: buf*ASZ (2 bufs) | B at 2*ASZ: buf*(2*BSZ) + plane*BSZ
    __shared__ int snode[BM];

    int tid = threadIdx.x;
    int w = tid >> 5, lane = tid & 31;
    int wm = w / WR_N, wn = w % WR_N;
    int warp_m0 = wm * WM, warp_n0 = wn * WN;

    // --- group / tile mapping (loop over ng groups) ---
    int bxr = blockIdx.x;
    int g = -1, cnt = 0, tile = 0;
#pragma unroll 1
    for (int gi = 0; gi < ng; gi++) {
        int cg = g_lab_cur[gbase + gi];
        int t = (cg + BM - 1) >> 7;
        if (bxr < t) { g = gbase + gi; cnt = cg; tile = bxr; break; }
        bxr -= t;
    }
    if (g < 0) return;
    int off = g * NMAX;
    int labl = g & 3;

    if (tid < BM) {
        int idx = tile * BM + tid;
        snode[tid] = (idx < cnt) ? g_perm[off + idx] : -1;
    }
    __syncthreads();

    const __half* WhiG = Whi + (size_t)labl * K * NOUT + blockIdx.y * BN;
    const __half* WloG = Wlo + (size_t)labl * K * NOUT + blockIdx.y * BN;

    int arow = tid >> 1, ahalf = tid & 1;
    int anode = snode[arow]; if (anode < 0) anode = 0;
    const TIN* aptr = X + (size_t)anode * K + ahalf * 16;

    int brow = tid >> 3, bcolg = tid & 7;
    constexpr int BPT = BN / 8;  // 16 or 8 halfs per thread

    uint32_t dyn_u = (uint32_t)__cvta_generic_to_shared(dyn);
    int a_m = lane & 15, a_koff = (lane >> 4) * 8;
    int b_k = lane & 15;

    float acc[M_TILES][N_TILES][4];
#pragma unroll
    for (int i = 0; i < M_TILES; i++)
#pragma unroll
        for (int j = 0; j < N_TILES; j++)
#pragma unroll
            for (int q = 0; q < 4; q++) acc[i][j][q] = 0.0f;

    float4 av32[4];
    uint4 av16[2];
    uint4 bh0, bh1, bl0, bl1;

    auto loadRegs = [&](int kc) {
        if (IN32) {
            const float* ap = (const float*)aptr + kc;
            av32[0] = *(const float4*)(ap);
            av32[1] = *(const float4*)(ap + 4);
            av32[2] = *(const float4*)(ap + 8);
            av32[3] = *(const float4*)(ap + 12);
        } else {
            const __half* ap = (const __half*)aptr + kc;
            av16[0] = *(const uint4*)(ap);
            av16[1] = *(const uint4*)(ap + 8);
        }
        const __half* ph = WhiG + (size_t)(kc + brow) * NOUT + bcolg * BPT;
        const __half* pl = WloG + (size_t)(kc + brow) * NOUT + bcolg * BPT;
        bh0 = *(const uint4*)ph;
        bl0 = *(const uint4*)pl;
        if (BPT == 16) {
            bh1 = *(const uint4*)(ph + 8);
            bl1 = *(const uint4*)(pl + 8);
        }
    };

    auto storeSmem = [&](int buf) {
        __half* da = dyn + buf * ASZ + arow * AS + ahalf * 16;
        if (IN32) {
            float f[16] = {av32[0].x, av32[0].y, av32[0].z, av32[0].w,
                           av32[1].x, av32[1].y, av32[1].z, av32[1].w,
                           av32[2].x, av32[2].y, av32[2].z, av32[2].w,
                           av32[3].x, av32[3].y, av32[3].z, av32[3].w};
            uint32_t p[8];
#pragma unroll
            for (int q = 0; q < 8; q++)
                p[q] = h2u(__floats2half2_rn(f[q * 2], f[q * 2 + 1]));
            ((uint4*)da)[0] = make_uint4(p[0], p[1], p[2], p[3]);
            ((uint4*)da)[1] = make_uint4(p[4], p[5], p[6], p[7]);
        } else {
            ((uint4*)da)[0] = av16[0];
            ((uint4*)da)[1] = av16[1];
        }
        __half* bh = dyn + 2 * ASZ + buf * (2 * BSZ) + brow * BS + bcolg * BPT;
        __half* bl = bh + BSZ;
        ((uint4*)bh)[0] = bh0;
        ((uint4*)bl)[0] = bl0;
        if (BPT == 16) {
            ((uint4*)bh)[1] = bh1;
            ((uint4*)bl)[1] = bl1;
        }
    };

    loadRegs(0);
    storeSmem(0);
    __syncthreads();

    for (int kc = 0; kc < CHUNKS; kc++) {
        int cur = kc & 1;
        if (kc + 1 < CHUNKS) loadRegs((kc + 1) * BK);

        uint32_t aBase = dyn_u + (uint32_t)(cur * ASZ) * 2;
        uint32_t bBase = dyn_u + (uint32_t)(2 * ASZ + cur * 2 * BSZ) * 2;
#pragma unroll
        for (int ks = 0; ks < 2; ks++) {
            uint32_t af[M_TILES][4];
            uint32_t bfh[N_TILES][2], bfl[N_TILES][2];
#pragma unroll
            for (int mt = 0; mt < M_TILES; mt++) {
                uint32_t ra = aBase + (uint32_t)((warp_m0 + mt * 16 + a_m) * AS + ks * 16 + a_koff) * 2;
                ldsm_x4(af[mt], ra);
            }
#pragma unroll
            for (int nt = 0; nt < N_TILES; nt++) {
                uint32_t rb = bBase + (uint32_t)((ks * 16 + b_k) * BS + warp_n0 + nt * 8) * 2;
                ldsm_x2t(bfh[nt], rb);
                ldsm_x2t(bfl[nt], rb + BSZ * 2);
            }
#pragma unroll
            for (int mt = 0; mt < M_TILES; mt++)
#pragma unroll
                for (int nt = 0; nt < N_TILES; nt++) {
                    mma_f16(acc[mt][nt], af[mt], bfh[nt]);
                    mma_f16(acc[mt][nt], af[mt], bfl[nt]);
                }
        }

        if (kc + 1 < CHUNKS) storeSmem(cur ^ 1);
        __syncthreads();
    }

    int grow = lane >> 2, gcol = (lane & 3) * 2;
#pragma unroll
    for (int mt = 0; mt < M_TILES; mt++) {
        int m1 = warp_m0 + mt * 16 + grow;
        int m2 = m1 + 8;
        int n1 = snode[m1], n2 = snode[m2];
#pragma unroll
        for (int nt = 0; nt < N_TILES; nt++) {
            int col = blockIdx.y * BN + warp_n0 + nt * 8 + gcol;
            if (n1 >= 0)
                *(__half2*)(S + (size_t)n1 * NOUT + col) =
                    __floats2half2_rn(acc[mt][nt][0], acc[mt][nt][1]);
            if (n2 >= 0)
                *(__half2*)(S + (size_t)n2 * NOUT + col) =
                    __floats2half2_rn(acc[mt][nt][2], acc[mt][nt][3]);
        }
    }
}

// ---------------- sparse aggregation: dst range [n0, n1) ----------------
template <int WID, typename TOUT>
__global__ void __launch_bounds__(256)
k_spmm(const __half* __restrict__ S, TOUT* __restrict__ O,
       const float* __restrict__ bias, int n0, int n1, int relu) {
    int wid = ((blockIdx.x * blockDim.x + threadIdx.x) >> 5) + n0;
    int lane = threadIdx.x & 31;
    if (wid >= n1) return;
    int s = g_row_ptr[wid], e = g_row_ptr[wid + 1];

    if (WID == 256) {
        float acc[8];
#pragma unroll
        for (int q = 0; q < 8; q++) acc[q] = 0.0f;

        int i = s;
        for (; i + 4 <= e; i += 4) {
            int s0 = g_csr_src[i], s1 = g_csr_src[i + 1];
            int s2 = g_csr_src[i + 2], s3 = g_csr_src[i + 3];
            float w0 = g_csr_w[i], w1 = g_csr_w[i + 1];
            float w2 = g_csr_w[i + 2], w3 = g_csr_w[i + 3];
            uint4 q0 = *(const uint4*)(S + (size_t)s0 * 256 + lane * 8);
            uint4 q1 = *(const uint4*)(S + (size_t)s1 * 256 + lane * 8);
            uint4 q2 = *(const uint4*)(S + (size_t)s2 * 256 + lane * 8);
            uint4 q3 = *(const uint4*)(S + (size_t)s3 * 256 + lane * 8);
#pragma unroll
            for (int h = 0; h < 4; h++) {
                float2 f0 = __half22float2(((const __half2*)&q0)[h]);
                float2 f1 = __half22float2(((const __half2*)&q1)[h]);
                float2 f2 = __half22float2(((const __half2*)&q2)[h]);
                float2 f3 = __half22float2(((const __half2*)&q3)[h]);
                acc[h * 2 + 0] = fmaf(w0, f0.x, acc[h * 2 + 0]);
                acc[h * 2 + 1] = fmaf(w0, f0.y, acc[h * 2 + 1]);
                acc[h * 2 + 0] = fmaf(w1, f1.x, acc[h * 2 + 0]);
                acc[h * 2 + 1] = fmaf(w1, f1.y, acc[h * 2 + 1]);
                acc[h * 2 + 0] = fmaf(w2, f2.x, acc[h * 2 + 0]);
                acc[h * 2 + 1] = fmaf(w2, f2.y, acc[h * 2 + 1]);
                acc[h * 2 + 0] = fmaf(w3, f3.x, acc[h * 2 + 0]);
                acc[h * 2 + 1] = fmaf(w3, f3.y, acc[h * 2 + 1]);
            }
        }
        for (; i < e; i++) {
            int s0 = g_csr_src[i];
            float w0 = g_csr_w[i];
            uint4 q0 = *(const uint4*)(S + (size_t)s0 * 256 + lane * 8);
#pragma unroll
            for (int h = 0; h < 4; h++) {
                float2 f0 = __half22float2(((const __half2*)&q0)[h]);
                acc[h * 2 + 0] = fmaf(w0, f0.x, acc[h * 2 + 0]);
                acc[h * 2 + 1] = fmaf(w0, f0.y, acc[h * 2 + 1]);
            }
        }
        float4 b0 = *(const float4*)(bias + lane * 8);
        float4 b1 = *(const float4*)(bias + lane * 8 + 4);
        acc[0] += b0.x; acc[1] += b0.y; acc[2] += b0.z; acc[3] += b0.w;
        acc[4] += b1.x; acc[5] += b1.y; acc[6] += b1.z; acc[7] += b1.w;
        if (relu) {
#pragma unroll
            for (int q = 0; q < 8; q++) acc[q] = fmaxf(acc[q], 0.0f);
        }
        if (sizeof(TOUT) == 4) {
            float* o = (float*)O + (size_t)wid * 256 + lane * 8;
            float4 v0 = {acc[0], acc[1], acc[2], acc[3]};
            float4 v1 = {acc[4], acc[5], acc[6], acc[7]};
            *(float4*)o = v0;
            *(float4*)(o + 4) = v1;
        } else {
            uint4 v;
            v.x = h2u(__floats2half2_rn(acc[0], acc[1]));
            v.y = h2u(__floats2half2_rn(acc[2], acc[3]));
            v.z = h2u(__floats2half2_rn(acc[4], acc[5]));
            v.w = h2u(__floats2half2_rn(acc[6], acc[7]));
            *(uint4*)((__half*)O + (size_t)wid * 256 + lane * 8) = v;
        }
    } else {  // WID == 64
        float2 acc = {0, 0};
        int i = s;
        for (; i + 4 <= e; i += 4) {
            int s0 = g_csr_src[i], s1 = g_csr_src[i + 1];
            int s2 = g_csr_src[i + 2], s3 = g_csr_src[i + 3];
            float w0 = g_csr_w[i], w1 = g_csr_w[i + 1];
            float w2 = g_csr_w[i + 2], w3 = g_csr_w[i + 3];
            __half2 h0 = *(const __half2*)(S + (size_t)s0 * 64 + lane * 2);
            __half2 h1 = *(const __half2*)(S + (size_t)s1 * 64 + lane * 2);
            __half2 h2 = *(const __half2*)(S + (size_t)s2 * 64 + lane * 2);
            __half2 h3 = *(const __half2*)(S + (size_t)s3 * 64 + lane * 2);
            float2 f0 = __half22float2(h0), f1 = __half22float2(h1);
            float2 f2 = __half22float2(h2), f3 = __half22float2(h3);
            acc.x = fmaf(w0, f0.x, acc.x); acc.y = fmaf(w0, f0.y, acc.y);
            acc.x = fmaf(w1, f1.x, acc.x); acc.y = fmaf(w1, f1.y, acc.y);
            acc.x = fmaf(w2, f2.x, acc.x); acc.y = fmaf(w2, f2.y, acc.y);
            acc.x = fmaf(w3, f3.x, acc.x); acc.y = fmaf(w3, f3.y, acc.y);
        }
        for (; i < e; i++) {
            int s0 = g_csr_src[i];
            float w0 = g_csr_w[i];
            float2 f0 = __half22float2(*(const __half2*)(S + (size_t)s0 * 64 + lane * 2));
            acc.x = fmaf(w0, f0.x, acc.x); acc.y = fmaf(w0, f0.y, acc.y);
        }
        float2 b = *(const float2*)(bias + lane * 2);
        acc.x += b.x; acc.y += b.y;
        if (relu) { acc.x = fmaxf(acc.x, 0.f); acc.y = fmaxf(acc.y, 0.f); }
        if (sizeof(TOUT) == 4) {
            *(float2*)((float*)O + (size_t)wid * 64 + lane * 2) = acc;
        } else {
            *(__half2*)((__half*)O + (size_t)wid * 64 + lane * 2) = __floats2half2_rn(acc.x, acc.y);
        }
    }
}

// ---------------- launch (EXACT R7 schedule — verified passing) ----------------
extern "C" void kernel_launch(void* const* d_in, const int* in_sizes, int n_in,
                              void* d_out, int out_size) {
    const float* x    = (const float*)d_in[0];
    const int*   esrc = (const int*)d_in[1];
    const int*   edst = (const int*)d_in[2];
    const float* ew   = (const float*)d_in[3];
    const int*   lab  = (const int*)d_in[4];
    const float* W1   = (const float*)d_in[5];
    const float* b1   = (const float*)d_in[6];
    const float* W2   = (const float*)d_in[7];
    const float* b2   = (const float*)d_in[8];
    const float* W3   = (const float*)d_in[9];
    const float* b3   = (const float*)d_in[10];
    float* out = (float*)d_out;

    int N = in_sizes[4];
    int E = in_sizes[1];
    int nh = N / 2;

    void *p_cnt, *p_cur, *p_H1, *p_H2, *p_F;
    void *p_w1h, *p_w1l, *p_w2h, *p_w2l, *p_w3h, *p_w3l;
    cudaGetSymbolAddress(&p_cnt, g_cnt);
    cudaGetSymbolAddress(&p_cur, g_lab_cur);
    cudaGetSymbolAddress(&p_H1, g_bufH1);
    cudaGetSymbolAddress(&p_H2, g_bufH2);
    cudaGetSymbolAddress(&p_F, g_bufF);
    cudaGetSymbolAddress(&p_w1h, g_W1hi); cudaGetSymbolAddress(&p_w1l, g_W1lo);
    cudaGetSymbolAddress(&p_w2h, g_W2hi); cudaGetSymbolAddress(&p_w2l, g_W2lo);
    cudaGetSymbolAddress(&p_w3h, g_W3hi); cudaGetSymbolAddress(&p_w3l, g_W3lo);
    __half* H1 = (__half*)p_H1;
    __half* H2 = (__half*)p_H2;
    __half* F  = (__half*)p_F;
    const __half *W1h = (const __half*)p_w1h, *W1l = (const __half*)p_w1l;
    const __half *W2h = (const __half*)p_w2h, *W2l = (const __half*)p_w2l;
    const __half *W3h = (const __half*)p_w3h, *W3l = (const __half*)p_w3l;

    // dynamic smem sizes: A one plane x2 bufs + B two planes x2 bufs
    const int ASZ = 128 * 40, BSZ128 = 32 * 136, BSZ64 = 32 * 72;
    const int SMEM_W = (2 * ASZ + 4 * BSZ128) * 2;   // 55296 B
    const int SMEM_N = (2 * ASZ + 4 * BSZ64) * 2;    // 38912 B
    cudaFuncSetAttribute(k_gemm_mma<128, float>,  cudaFuncAttributeMaxDynamicSharedMemorySize, SMEM_W);
    cudaFuncSetAttribute(k_gemm_mma<128, __half>, cudaFuncAttributeMaxDynamicSharedMemorySize, SMEM_W);
    cudaFuncSetAttribute(k_gemm_mma<64, __half>,  cudaFuncAttributeMaxDynamicSharedMemorySize, SMEM_N);

    static cudaStream_t s2 = nullptr;
    static cudaEvent_t evFork, evJoin, evW, evG1, evS1b, evG2, evS2b, evG3, evS3b;
    if (s2 == nullptr) {
        cudaStreamCreateWithFlags(&s2, cudaStreamNonBlocking);
        cudaEventCreateWithFlags(&evFork, cudaEventDisableTiming);
        cudaEventCreateWithFlags(&evJoin, cudaEventDisableTiming);
        cudaEventCreateWithFlags(&evW, cudaEventDisableTiming);
        cudaEventCreateWithFlags(&evG1, cudaEventDisableTiming);
        cudaEventCreateWithFlags(&evS1b, cudaEventDisableTiming);
        cudaEventCreateWithFlags(&evG2, cudaEventDisableTiming);
        cudaEventCreateWithFlags(&evS2b, cudaEventDisableTiming);
        cudaEventCreateWithFlags(&evG3, cudaEventDisableTiming);
        cudaEventCreateWithFlags(&evS3b, cudaEventDisableTiming);
    }

    const int tpb = 256;
    int rtF = (N + 127) / 128 + 8;       // full (8 groups)
    int rtH = (nh + 255) / 128 + 4;      // half (4 groups), generous
    int spA = (nh * 32 + tpb - 1) / tpb;          // dst [0, nh)
    int spB = ((N - nh) * 32 + tpb - 1) / tpb;    // dst [nh, N)

    // ---- fork ----
    cudaEventRecord(evFork, 0);
    cudaStreamWaitEvent(s2, evFork, 0);

    // s2: CSR build, then weight splits
    cudaMemsetAsync(p_cnt, 0, (size_t)N * sizeof(int), s2);
    k_hist_edges<<<1024, tpb, 0, s2>>>(edst, E);
    k_scan_rows<<<1, 1024, 0, s2>>>(N);
    k_scatter_edges<<<1024, tpb, 0, s2>>>(esrc, edst, ew, E);
    cudaEventRecord(evJoin, s2);
    k_wsplit<<<256, tpb, 0, s2>>>(W2, (__half*)p_w2h, (__half*)p_w2l, 4 * 256 * 256);
    k_wsplit<<<64, tpb, 0, s2>>>(W3, (__half*)p_w3h, (__half*)p_w3l, 4 * 256 * 64);
    cudaEventRecord(evW, s2);

    // main: grouping + W1 split + GEMM1 (full)
    cudaMemsetAsync(p_cur, 0, 8 * sizeof(int), 0);
    k_scatter_perm8<<<(N + tpb - 1) / tpb, tpb>>>(lab, N, nh);
    k_wsplit<<<256, tpb>>>(W1, (__half*)p_w1h, (__half*)p_w1l, 4 * 256 * 256);
    k_gemm_mma<128, float><<<dim3(rtF, 2), 256, SMEM_W>>>(x, W1h, W1l, H1, 256, 0, 8);
    cudaEventRecord(evG1, 0);

    // main: SpMM1a needs CSR
    cudaStreamWaitEvent(0, evJoin, 0);
    k_spmm<256, __half><<<spA, tpb>>>(H1, F, b1, 0, nh, 1);

    // s2: SpMM1b (CSR in program order; needs GEMM1)
    cudaStreamWaitEvent(s2, evG1, 0);
    k_spmm<256, __half><<<spB, tpb, 0, s2>>>(H1, F, b1, nh, N, 1);
    cudaEventRecord(evS1b, s2);

    // main: GEMM2a (half0) overlaps SpMM1b
    cudaStreamWaitEvent(0, evW, 0);
    k_gemm_mma<128, __half><<<dim3(rtH, 2), 256, SMEM_W>>>(F, W2h, W2l, H2, 256, 0, 4);
    cudaStreamWaitEvent(0, evS1b, 0);
    k_gemm_mma<128, __half><<<dim3(rtH, 2), 256, SMEM_W>>>(F, W2h, W2l, H2, 256, 4, 4);
    cudaEventRecord(evG2, 0);

    // main: SpMM2a; s2: SpMM2b
    k_spmm<256, __half><<<spA, tpb>>>(H2, F, b2, 0, nh, 1);
    cudaStreamWaitEvent(s2, evG2, 0);
    k_spmm<256, __half><<<spB, tpb, 0, s2>>>(H2, F, b2, nh, N, 1);
    cudaEventRecord(evS2b, s2);

    // main: GEMM3a overlaps SpMM2b
    k_gemm_mma<64, __half><<<dim3(rtH, 1), 256, SMEM_N>>>(F, W3h, W3l, H1, 64, 0, 4);
    cudaStreamWaitEvent(0, evS2b, 0);
    k_gemm_mma<64, __half><<<dim3(rtH, 1), 256, SMEM_N>>>(F, W3h, W3l, H1, 64, 4, 4);
    cudaEventRecord(evG3, 0);

    // SpMM3 split across streams
    k_spmm<64, float><<<spA, tpb>>>(H1, out, b3, 0, nh, 0);
    cudaStreamWaitEvent(s2, evG3, 0);
    k_spmm<64, float><<<spB, tpb, 0, s2>>>(H1, out, b3, nh, N, 0);
    cudaEventRecord(evS3b, s2);
    cudaStreamWaitEvent(0, evS3b, 0);
}